// round 3
// baseline (speedup 1.0000x reference)
#include <cuda_runtime.h>
#include <cuda_bf16.h>

#define N_NODES 100000
#define N_EDGES 1600000
#define IN_CH   128
#define OUT_CH  64
#define SCAN_T  512
#define SB ((N_NODES + SCAN_T - 1) / SCAN_T)   /* 196 */
#define EB ((N_EDGES + 255) / 256)             /* 6250 */

// ---------------- device scratch (static, allocation-free) ----------------
__device__ float g_W23[IN_CH * OUT_CH];     // W2@W3   [128,64]
__device__ float g_Wc[IN_CH * OUT_CH];      // W1@W23  [128,64]
__device__ int   g_col[N_EDGES];            // src ids grouped by dst (CSR cols)
__device__ int   g_off[N_NODES + 1];        // CSR row offsets
__device__ int   g_cnt[N_NODES];            // histogram -> cursor
__device__ int   g_bsum[SB];                // scan block partials
__device__ float g_t[N_NODES * OUT_CH];     // ping
__device__ float g_y[N_NODES * OUT_CH];     // pong
__device__ int   g_is64;

// ---------------- zero histogram + dtype detect ----------------
__global__ void k_zero_detect(const int* ei) {
    int idx = blockIdx.x * blockDim.x + threadIdx.x;
    if (idx < N_NODES) g_cnt[idx] = 0;
    if (idx == 0) {
        int is64 = 1;
        for (int i = 0; i < 64; i++) {
            if (ei[2 * i + 1] != 0) { is64 = 0; break; }
        }
        g_is64 = is64;
    }
}

// ---------------- hist (reads edge_index dst-half directly) ∥ W23 = W2@W3 ----
__global__ void k_hist_w23(const void* ei, const float* __restrict__ W2,
                           const float* __restrict__ W3) {
    if (blockIdx.x < EB) {
        int e = blockIdx.x * 256 + threadIdx.x;
        if (e < N_EDGES) {
            int d;
            if (g_is64) d = (int)((const long long*)ei)[(long long)N_EDGES + e];
            else        d = ((const int*)ei)[N_EDGES + e];
            atomicAdd(&g_cnt[d], 1);
        }
    } else {
        int k = blockIdx.x - EB;       // 0..127
        int j = threadIdx.x;
        if (j < OUT_CH) {
            float s = 0.f;
#pragma unroll 8
            for (int m = 0; m < IN_CH; m++)
                s += W2[k * IN_CH + m] * W3[m * OUT_CH + j];
            g_W23[k * OUT_CH + j] = s;
        }
    }
}

// ---------------- scan1 (warp-shuffle block scan) ∥ Wc = W1@W23 ----------------
__global__ void k_scan1_wc(const float* __restrict__ W1) {
    int t = threadIdx.x;
    if (blockIdx.x < SB) {
        int idx = blockIdx.x * SCAN_T + t;
        int v = (idx < N_NODES) ? g_cnt[idx] : 0;
        int lane = t & 31, w = t >> 5;
        int xv = v;
#pragma unroll
        for (int o = 1; o < 32; o <<= 1) {
            int n = __shfl_up_sync(0xFFFFFFFFu, xv, o);
            if (lane >= o) xv += n;
        }
        __shared__ int wsum[16];
        if (lane == 31) wsum[w] = xv;
        __syncthreads();
        if (w == 0) {
            int s = (lane < 16) ? wsum[lane] : 0;
#pragma unroll
            for (int o = 1; o < 16; o <<= 1) {
                int n = __shfl_up_sync(0xFFFFFFFFu, s, o);
                if (lane >= o) s += n;
            }
            if (lane < 16) wsum[lane] = s;   // inclusive warp sums
        }
        __syncthreads();
        int base = (w > 0) ? wsum[w - 1] : 0;
        int incl = xv + base;
        if (idx < N_NODES) g_off[idx] = incl - v;     // exclusive (local)
        if (t == SCAN_T - 1) g_bsum[blockIdx.x] = incl;
    } else {
        int k = blockIdx.x - SB;       // 0..127
        if (t < OUT_CH) {
            float s = 0.f;
#pragma unroll 8
            for (int m = 0; m < IN_CH; m++)
                s += W1[k * IN_CH + m] * g_W23[m * OUT_CH + t];
            g_Wc[k * OUT_CH + t] = s;
        }
    }
}

// ---------------- scan2: one block scans the 196 partials (no serial L2 walk) --
__global__ void k_scan2() {
    __shared__ int s[256];
    int t = threadIdx.x;
    int v = (t < SB) ? g_bsum[t] : 0;
    s[t] = v;
    __syncthreads();
    for (int o = 1; o < 256; o <<= 1) {
        int a = (t >= o) ? s[t - o] : 0;
        __syncthreads();
        s[t] += a;
        __syncthreads();
    }
    if (t < SB) g_bsum[t] = s[t] - v;   // exclusive block prefix
}

// ---------------- scan3: finalize offsets + init cursors ----------------
__global__ void k_scan3() {
    int idx = blockIdx.x * SCAN_T + threadIdx.x;
    if (idx < N_NODES) {
        int v = g_off[idx] + g_bsum[blockIdx.x];
        g_off[idx] = v;
        g_cnt[idx] = v;
    }
    if (idx == 0) g_off[N_NODES] = N_EDGES;
}

// ---------------- fill CSR (reads edge_index directly) ----------------
__global__ void k_fill(const void* ei) {
    int e = blockIdx.x * 256 + threadIdx.x;
    if (e < N_EDGES) {
        int s, d;
        if (g_is64) {
            const long long* p = (const long long*)ei;
            s = (int)p[e];
            d = (int)p[(long long)N_EDGES + e];
        } else {
            const int* p = (const int*)ei;
            s = p[e];
            d = p[N_EDGES + e];
        }
        int pos = atomicAdd(&g_cnt[d], 1);
        g_col[pos] = s;
    }
}

// ---------------- GEMM: t = x[100000,128] @ Wc[128,64] ----------------
// BM=128, BN=64(all), BK=32; 128 threads, 8x8 per thread; Wc smem-resident;
// A stored transposed with XOR swizzle (conflict-free, float4-aligned).
#define BM 128
#define BK 32
__global__ __launch_bounds__(128) void k_gemm(const float* __restrict__ x) {
    __shared__ float Bs[IN_CH][OUT_CH];   // 32KB, whole Wc
    __shared__ float XsT[BK][BM];         // 16KB, [k][row^swz]
    int tid = threadIdx.x;
    int row0 = blockIdx.x * BM;

    // load Wc fully (2048 float4, 16 per thread)
    {
        const float4* src = (const float4*)g_Wc;
        float4* dstp = (float4*)&Bs[0][0];
#pragma unroll
        for (int i = 0; i < 16; i++) dstp[i * 128 + tid] = src[i * 128 + tid];
    }

    int ty = tid >> 3;   // 0..15 -> rows ty*8..+7
    int tx = tid & 7;    // 0..7  -> cols tx*8..+7
    int kq = tid & 7;    // float4 idx within 32-k chunk (loader role)
    int r0 = tid >> 3;   // base row for loads

    float acc[8][8];
#pragma unroll
    for (int i = 0; i < 8; i++)
#pragma unroll
        for (int j = 0; j < 8; j++) acc[i][j] = 0.f;

    __syncthreads();

    for (int kc = 0; kc < IN_CH; kc += BK) {
        // load A chunk: 128 rows x 32 k, coalesced; store swizzled transpose
        int swzs = kq << 2;   // bits 2..4
#pragma unroll
        for (int i = 0; i < 8; i++) {
            int r = r0 + i * 16;
            int grow = row0 + r;
            float4 v = make_float4(0.f, 0.f, 0.f, 0.f);
            if (grow < N_NODES)
                v = *(const float4*)&x[(size_t)grow * IN_CH + kc + kq * 4];
            int c = r ^ swzs;
            XsT[kq * 4 + 0][c] = v.x;
            XsT[kq * 4 + 1][c] = v.y;
            XsT[kq * 4 + 2][c] = v.z;
            XsT[kq * 4 + 3][c] = v.w;
        }
        __syncthreads();
#pragma unroll
        for (int k = 0; k < BK; k++) {
            int swz = ((k >> 2) & 7) << 2;
            float4 a0 = *(const float4*)&XsT[k][(ty * 8) ^ swz];
            float4 a1 = *(const float4*)&XsT[k][(ty * 8 + 4) ^ swz];
            float4 b0 = *(const float4*)&Bs[kc + k][tx * 8];
            float4 b1 = *(const float4*)&Bs[kc + k][tx * 8 + 4];
            float ar[8] = {a0.x, a0.y, a0.z, a0.w, a1.x, a1.y, a1.z, a1.w};
            float br[8] = {b0.x, b0.y, b0.z, b0.w, b1.x, b1.y, b1.z, b1.w};
#pragma unroll
            for (int i = 0; i < 8; i++)
#pragma unroll
                for (int j = 0; j < 8; j++) acc[i][j] += ar[i] * br[j];
        }
        __syncthreads();
    }

#pragma unroll
    for (int i = 0; i < 8; i++) {
        int grow = row0 + ty * 8 + i;
        if (grow < N_NODES) {
            float4 o0 = make_float4(acc[i][0], acc[i][1], acc[i][2], acc[i][3]);
            float4 o1 = make_float4(acc[i][4], acc[i][5], acc[i][6], acc[i][7]);
            *(float4*)&g_t[(size_t)grow * OUT_CH + tx * 8] = o0;
            *(float4*)&g_t[(size_t)grow * OUT_CH + tx * 8 + 4] = o1;
        }
    }
}

// ---------------- CSR aggregation: out[n] = sum_{e in row n} in[col[e]] ----------------
// phase 0: g_t -> g_y ; phase 1: g_y -> g_t ; phase 2: g_t -> out_final
__global__ __launch_bounds__(256) void k_agg(int phase, float* __restrict__ out_final) {
    const float* __restrict__ in = (phase == 1) ? g_y : g_t;
    float* __restrict__ out = (phase == 0) ? g_y : (phase == 1) ? g_t : out_final;

    int tid = blockIdx.x * blockDim.x + threadIdx.x;
    int node = tid >> 4;
    int l = tid & 15;
    if (node >= N_NODES) return;
    int s = g_off[node];
    int e = g_off[node + 1];
    float4 acc = make_float4(0.f, 0.f, 0.f, 0.f);
    int i = s;
    for (; i + 4 <= e; i += 4) {
        int c0 = __ldg(&g_col[i]);
        int c1 = __ldg(&g_col[i + 1]);
        int c2 = __ldg(&g_col[i + 2]);
        int c3 = __ldg(&g_col[i + 3]);
        float4 v0 = *(const float4*)&in[c0 * OUT_CH + l * 4];
        float4 v1 = *(const float4*)&in[c1 * OUT_CH + l * 4];
        float4 v2 = *(const float4*)&in[c2 * OUT_CH + l * 4];
        float4 v3 = *(const float4*)&in[c3 * OUT_CH + l * 4];
        acc.x += (v0.x + v1.x) + (v2.x + v3.x);
        acc.y += (v0.y + v1.y) + (v2.y + v3.y);
        acc.z += (v0.z + v1.z) + (v2.z + v3.z);
        acc.w += (v0.w + v1.w) + (v2.w + v3.w);
    }
    for (; i < e; i++) {
        int c = __ldg(&g_col[i]);
        float4 v = *(const float4*)&in[c * OUT_CH + l * 4];
        acc.x += v.x; acc.y += v.y; acc.z += v.z; acc.w += v.w;
    }
    *(float4*)&out[node * OUT_CH + l * 4] = acc;
}

// ---------------- launch ----------------
extern "C" void kernel_launch(void* const* d_in, const int* in_sizes, int n_in,
                              void* d_out, int out_size) {
    const float* x  = (const float*)d_in[0];
    const void*  ei = d_in[1];
    const float* W1 = (const float*)d_in[2];
    const float* W2 = (const float*)d_in[3];
    const float* W3 = (const float*)d_in[4];
    float* out = (float*)d_out;

    const int ZB = (N_NODES + 1023) / 1024;          // 98
    const int GB = (N_NODES + BM - 1) / BM;          // 782
    const int AB = (N_NODES * 16 + 255) / 256;       // 6250

    k_zero_detect<<<ZB, 1024>>>((const int*)ei);
    k_hist_w23<<<EB + 128, 256>>>(ei, W2, W3);
    k_scan1_wc<<<SB + 128, SCAN_T>>>(W1);
    k_scan2<<<1, 256>>>();
    k_scan3<<<SB, SCAN_T>>>();
    k_fill<<<EB, 256>>>(ei);

    k_gemm<<<GB, 128>>>(x);

    k_agg<<<AB, 256>>>(0, out);
    k_agg<<<AB, 256>>>(1, out);
    k_agg<<<AB, 256>>>(2, out);
}

// round 4
// speedup vs baseline: 1.2432x; 1.2432x over previous
#include <cuda_runtime.h>
#include <cuda_bf16.h>

#define N_NODES 100000
#define N_EDGES 1600000
#define IN_CH   128
#define OUT_CH  64
#define SCAN_T  512
#define SB ((N_NODES + SCAN_T - 1) / SCAN_T)   /* 196 */

// ---------------- device scratch (static, allocation-free) ----------------
__device__ float g_Wtmp[IN_CH * IN_CH];     // W1@W2  [128,128]
__device__ float g_Wc[IN_CH * OUT_CH];      // W1@W2@W3 [128,64]
__device__ int   g_src[N_EDGES];
__device__ int   g_dst[N_EDGES];
__device__ int   g_col[N_EDGES];            // src ids grouped by dst (CSR cols)
__device__ int   g_off[N_NODES + 1];        // CSR row offsets
__device__ int   g_cnt[N_NODES];            // histogram, then cursor
__device__ int   g_bsum[256];               // scan block partials
__device__ float g_t[N_NODES * OUT_CH];     // ping
__device__ float g_y[N_NODES * OUT_CH];     // pong
__device__ int   g_is64;

// ---------------- dtype detection ----------------
__global__ void k_detect(const int* ei) {
    if (threadIdx.x == 0 && blockIdx.x == 0) {
        int is64 = 1;
        for (int i = 0; i < 64; i++) {
            if (ei[2 * i + 1] != 0) { is64 = 0; break; }
        }
        g_is64 = is64;
    }
}

// ---------------- convert edge_index -> int32, zero histogram ----------------
__global__ void k_convert(const void* ei) {
    int is64 = g_is64;
    int tid = blockIdx.x * blockDim.x + threadIdx.x;
    int stride = gridDim.x * blockDim.x;
    for (int e = tid; e < N_EDGES; e += stride) {
        int s, d;
        if (is64) {
            const long long* p = (const long long*)ei;
            s = (int)p[e];
            d = (int)p[(long long)N_EDGES + e];
        } else {
            const int* p = (const int*)ei;
            s = p[e];
            d = p[N_EDGES + e];
        }
        g_src[e] = s;
        g_dst[e] = d;
    }
    for (int i = tid; i < N_NODES; i += stride) g_cnt[i] = 0;
}

__global__ void k_hist() {
    int e = blockIdx.x * blockDim.x + threadIdx.x;
    if (e < N_EDGES) atomicAdd(&g_cnt[g_dst[e]], 1);
}

// ---------------- exclusive scan ----------------
__global__ void k_scan1() {
    __shared__ int s[SCAN_T];
    int t = threadIdx.x;
    int idx = blockIdx.x * SCAN_T + t;
    int v = (idx < N_NODES) ? g_cnt[idx] : 0;
    s[t] = v;
    __syncthreads();
    for (int o = 1; o < SCAN_T; o <<= 1) {
        int add = (t >= o) ? s[t - o] : 0;
        __syncthreads();
        s[t] += add;
        __syncthreads();
    }
    if (idx < N_NODES) g_off[idx] = s[t] - v;   // exclusive (local)
    if (t == SCAN_T - 1) g_bsum[blockIdx.x] = s[t];
}

// one block scans the 196 block partials in smem (replaces serial L2 walk)
__global__ void k_scan2() {
    __shared__ int s[256];
    int t = threadIdx.x;
    int v = (t < SB) ? g_bsum[t] : 0;
    s[t] = v;
    __syncthreads();
    for (int o = 1; o < 256; o <<= 1) {
        int a = (t >= o) ? s[t - o] : 0;
        __syncthreads();
        s[t] += a;
        __syncthreads();
    }
    if (t < SB) g_bsum[t] = s[t] - v;   // exclusive prefix of block sums
}

// finalize offsets + init fill cursors (fused)
__global__ void k_scan3() {
    int idx = blockIdx.x * SCAN_T + threadIdx.x;
    if (idx < N_NODES) {
        int v = g_off[idx] + g_bsum[blockIdx.x];
        g_off[idx] = v;
        g_cnt[idx] = v;
    }
    if (idx == 0) g_off[N_NODES] = N_EDGES;
}

__global__ void k_fill() {
    int e = blockIdx.x * blockDim.x + threadIdx.x;
    if (e < N_EDGES) {
        int d = g_dst[e];
        int p = atomicAdd(&g_cnt[d], 1);
        g_col[p] = g_src[e];
    }
}

// ---------------- weight chain: Wtmp = W1@W2 ; Wc = Wtmp@W3 ----------------
__global__ void k_w1w2(const float* __restrict__ W1, const float* __restrict__ W2) {
    int k = blockIdx.x;      // 0..127
    int j = threadIdx.x;     // 0..127
    float s = 0.f;
#pragma unroll 8
    for (int m = 0; m < IN_CH; m++)
        s += W1[k * IN_CH + m] * W2[m * IN_CH + j];
    g_Wtmp[k * IN_CH + j] = s;
}
__global__ void k_wc(const float* __restrict__ W3) {
    int k = blockIdx.x;      // 0..127
    int j = threadIdx.x;     // 0..63
    float s = 0.f;
#pragma unroll 8
    for (int m = 0; m < IN_CH; m++)
        s += g_Wtmp[k * IN_CH + m] * W3[m * OUT_CH + j];
    g_Wc[k * OUT_CH + j] = s;
}

// ---------------- GEMM: t[100000,64] = x[100000,128] @ Wc[128,64] ----------------
// (R2 version, known-good) block tile M=64, N=64, K chunks of 64; 256 thr, 4x4/thr
#define GM 64
#define GK 64
__global__ __launch_bounds__(256) void k_gemm(const float* __restrict__ x) {
    __shared__ float XsT[GK][GM + 4];   // transposed: [k][row]
    __shared__ float Ws[GK][OUT_CH];    // [k][col]
    int row0 = blockIdx.x * GM;
    int tid = threadIdx.x;
    int ty = tid >> 4;        // 0..15 -> rows ty*4..+3
    int tx = tid & 15;        // 0..15 -> cols tx*4..+3
    float acc[4][4];
#pragma unroll
    for (int i = 0; i < 4; i++)
#pragma unroll
        for (int j = 0; j < 4; j++) acc[i][j] = 0.f;

    for (int kc = 0; kc < IN_CH; kc += GK) {
#pragma unroll
        for (int i = 0; i < 4; i++) {
            int slot = tid + i * 256;           // 0..1023 float4 slots
            int r = slot >> 4;                  // row 0..63
            int kq = slot & 15;                 // float4 idx within 64 k
            int grow = row0 + r;
            float4 v = make_float4(0.f, 0.f, 0.f, 0.f);
            if (grow < N_NODES)
                v = *(const float4*)&x[(long long)grow * IN_CH + kc + kq * 4];
            XsT[kq * 4 + 0][r] = v.x;
            XsT[kq * 4 + 1][r] = v.y;
            XsT[kq * 4 + 2][r] = v.z;
            XsT[kq * 4 + 3][r] = v.w;
        }
#pragma unroll
        for (int i = 0; i < 4; i++) {
            int slot = tid + i * 256;
            int k = slot >> 4;
            int nq = slot & 15;
            *(float4*)&Ws[k][nq * 4] =
                *(const float4*)&g_Wc[(kc + k) * OUT_CH + nq * 4];
        }
        __syncthreads();
#pragma unroll
        for (int k = 0; k < GK; k++) {
            float4 a = *(const float4*)&XsT[k][ty * 4];
            float4 b = *(const float4*)&Ws[k][tx * 4];
            float ar[4] = {a.x, a.y, a.z, a.w};
            float br[4] = {b.x, b.y, b.z, b.w};
#pragma unroll
            for (int i = 0; i < 4; i++)
#pragma unroll
                for (int j = 0; j < 4; j++) acc[i][j] += ar[i] * br[j];
        }
        __syncthreads();
    }
#pragma unroll
    for (int i = 0; i < 4; i++) {
        int grow = row0 + ty * 4 + i;
        if (grow < N_NODES) {
            float4 o = make_float4(acc[i][0], acc[i][1], acc[i][2], acc[i][3]);
            *(float4*)&g_t[(long long)grow * OUT_CH + tx * 4] = o;
        }
    }
}

// ---------------- CSR aggregation ----------------
// phase 0: g_t -> g_y ; phase 1: g_y -> g_t ; phase 2: g_t -> out_final
// device-side resolution of global symbol pointers (host symbols invalid).
__global__ __launch_bounds__(256) void k_agg(int phase, float* __restrict__ out_final) {
    const float* __restrict__ in = (phase == 1) ? g_y : g_t;
    float* __restrict__ out = (phase == 0) ? g_y : (phase == 1) ? g_t : out_final;

    int tid = blockIdx.x * blockDim.x + threadIdx.x;
    int node = tid >> 4;
    int l = tid & 15;
    if (node >= N_NODES) return;
    int s = g_off[node];
    int e = g_off[node + 1];
    float4 acc = make_float4(0.f, 0.f, 0.f, 0.f);
    int i = s;
    for (; i + 4 <= e; i += 4) {
        int c0 = __ldg(&g_col[i]);
        int c1 = __ldg(&g_col[i + 1]);
        int c2 = __ldg(&g_col[i + 2]);
        int c3 = __ldg(&g_col[i + 3]);
        float4 v0 = *(const float4*)&in[c0 * OUT_CH + l * 4];
        float4 v1 = *(const float4*)&in[c1 * OUT_CH + l * 4];
        float4 v2 = *(const float4*)&in[c2 * OUT_CH + l * 4];
        float4 v3 = *(const float4*)&in[c3 * OUT_CH + l * 4];
        acc.x += (v0.x + v1.x) + (v2.x + v3.x);
        acc.y += (v0.y + v1.y) + (v2.y + v3.y);
        acc.z += (v0.z + v1.z) + (v2.z + v3.z);
        acc.w += (v0.w + v1.w) + (v2.w + v3.w);
    }
    for (; i < e; i++) {
        int c = __ldg(&g_col[i]);
        float4 v = *(const float4*)&in[c * OUT_CH + l * 4];
        acc.x += v.x; acc.y += v.y; acc.z += v.z; acc.w += v.w;
    }
    *(float4*)&out[node * OUT_CH + l * 4] = acc;
}

// ---------------- launch ----------------
extern "C" void kernel_launch(void* const* d_in, const int* in_sizes, int n_in,
                              void* d_out, int out_size) {
    const float* x  = (const float*)d_in[0];
    const void*  ei = d_in[1];
    const float* W1 = (const float*)d_in[2];
    const float* W2 = (const float*)d_in[3];
    const float* W3 = (const float*)d_in[4];
    float* out = (float*)d_out;

    const int EB = (N_EDGES + 255) / 256;            // 6250
    const int GB = (N_NODES + GM - 1) / GM;          // 1563
    const int AB = (N_NODES * 16 + 255) / 256;       // 6250

    k_detect<<<1, 32>>>((const int*)ei);
    k_convert<<<2048, 256>>>(ei);
    k_hist<<<EB, 256>>>();
    k_scan1<<<SB, SCAN_T>>>();
    k_scan2<<<1, 256>>>();
    k_scan3<<<SB, SCAN_T>>>();
    k_fill<<<EB, 256>>>();

    k_w1w2<<<IN_CH, IN_CH>>>(W1, W2);
    k_wc<<<IN_CH, OUT_CH>>>(W3);
    k_gemm<<<GB, 256>>>(x);

    k_agg<<<AB, 256>>>(0, out);
    k_agg<<<AB, 256>>>(1, out);
    k_agg<<<AB, 256>>>(2, out);
}

// round 5
// speedup vs baseline: 1.3361x; 1.0747x over previous
#include <cuda_runtime.h>
#include <cuda_bf16.h>
#include <cuda_fp16.h>

#define N_NODES 100000
#define N_EDGES 1600000
#define IN_CH   128
#define OUT_CH  64
#define SCAN_T  512
#define SB ((N_NODES + SCAN_T - 1) / SCAN_T)   /* 196 */

// ---------------- device scratch (static, allocation-free) ----------------
__device__ float  g_Wtmp[IN_CH * IN_CH];     // W1@W2  [128,128]
__device__ float  g_Wc[IN_CH * OUT_CH];      // W1@W2@W3 [128,64]
__device__ int    g_src[N_EDGES];
__device__ int    g_dst[N_EDGES];
__device__ int    g_col[N_EDGES];            // src ids grouped by dst (CSR cols)
__device__ int    g_off[N_NODES + 1];        // CSR row offsets
__device__ int    g_cnt[N_NODES];            // histogram, then cursor
__device__ int    g_bsum[256];               // scan block partials
__device__ __half g_t[N_NODES * OUT_CH];     // ping (fp16 features)
__device__ __half g_y[N_NODES * OUT_CH];     // pong (fp16 features)
__device__ int    g_is64;

// ---------------- dtype detection ----------------
__global__ void k_detect(const int* ei) {
    if (threadIdx.x == 0 && blockIdx.x == 0) {
        int is64 = 1;
        for (int i = 0; i < 64; i++) {
            if (ei[2 * i + 1] != 0) { is64 = 0; break; }
        }
        g_is64 = is64;
    }
}

// ---------------- convert edge_index -> int32, zero histogram ----------------
__global__ void k_convert(const void* ei) {
    int is64 = g_is64;
    int tid = blockIdx.x * blockDim.x + threadIdx.x;
    int stride = gridDim.x * blockDim.x;
    for (int e = tid; e < N_EDGES; e += stride) {
        int s, d;
        if (is64) {
            const long long* p = (const long long*)ei;
            s = (int)p[e];
            d = (int)p[(long long)N_EDGES + e];
        } else {
            const int* p = (const int*)ei;
            s = p[e];
            d = p[N_EDGES + e];
        }
        g_src[e] = s;
        g_dst[e] = d;
    }
    for (int i = tid; i < N_NODES; i += stride) g_cnt[i] = 0;
}

__global__ void k_hist() {
    int e = blockIdx.x * blockDim.x + threadIdx.x;
    if (e < N_EDGES) atomicAdd(&g_cnt[g_dst[e]], 1);
}

// ---------------- exclusive scan ----------------
__global__ void k_scan1() {
    __shared__ int s[SCAN_T];
    int t = threadIdx.x;
    int idx = blockIdx.x * SCAN_T + t;
    int v = (idx < N_NODES) ? g_cnt[idx] : 0;
    s[t] = v;
    __syncthreads();
    for (int o = 1; o < SCAN_T; o <<= 1) {
        int add = (t >= o) ? s[t - o] : 0;
        __syncthreads();
        s[t] += add;
        __syncthreads();
    }
    if (idx < N_NODES) g_off[idx] = s[t] - v;   // exclusive (local)
    if (t == SCAN_T - 1) g_bsum[blockIdx.x] = s[t];
}

// one block scans the 196 block partials in smem
__global__ void k_scan2() {
    __shared__ int s[256];
    int t = threadIdx.x;
    int v = (t < SB) ? g_bsum[t] : 0;
    s[t] = v;
    __syncthreads();
    for (int o = 1; o < 256; o <<= 1) {
        int a = (t >= o) ? s[t - o] : 0;
        __syncthreads();
        s[t] += a;
        __syncthreads();
    }
    if (t < SB) g_bsum[t] = s[t] - v;   // exclusive prefix of block sums
}

// finalize offsets + init fill cursors (fused)
__global__ void k_scan3() {
    int idx = blockIdx.x * SCAN_T + threadIdx.x;
    if (idx < N_NODES) {
        int v = g_off[idx] + g_bsum[blockIdx.x];
        g_off[idx] = v;
        g_cnt[idx] = v;
    }
    if (idx == 0) g_off[N_NODES] = N_EDGES;
}

__global__ void k_fill() {
    int e = blockIdx.x * blockDim.x + threadIdx.x;
    if (e < N_EDGES) {
        int d = g_dst[e];
        int p = atomicAdd(&g_cnt[d], 1);
        g_col[p] = g_src[e];
    }
}

// ---------------- weight chain: Wtmp = W1@W2 ; Wc = Wtmp@W3 ----------------
__global__ void k_w1w2(const float* __restrict__ W1, const float* __restrict__ W2) {
    int k = blockIdx.x;      // 0..127
    int j = threadIdx.x;     // 0..127
    float s = 0.f;
#pragma unroll 8
    for (int m = 0; m < IN_CH; m++)
        s += W1[k * IN_CH + m] * W2[m * IN_CH + j];
    g_Wtmp[k * IN_CH + j] = s;
}
__global__ void k_wc(const float* __restrict__ W3) {
    int k = blockIdx.x;      // 0..127
    int j = threadIdx.x;     // 0..63
    float s = 0.f;
#pragma unroll 8
    for (int m = 0; m < IN_CH; m++)
        s += g_Wtmp[k * IN_CH + m] * W3[m * OUT_CH + j];
    g_Wc[k * OUT_CH + j] = s;
}

// ---------------- GEMM: t[100000,64] = x[100000,128] @ Wc[128,64] (fp16 out) --
#define GM 64
#define GK 64
__global__ __launch_bounds__(256) void k_gemm(const float* __restrict__ x) {
    __shared__ float XsT[GK][GM + 4];   // transposed: [k][row]
    __shared__ float Ws[GK][OUT_CH];    // [k][col]
    int row0 = blockIdx.x * GM;
    int tid = threadIdx.x;
    int ty = tid >> 4;        // 0..15 -> rows ty*4..+3
    int tx = tid & 15;        // 0..15 -> cols tx*4..+3
    float acc[4][4];
#pragma unroll
    for (int i = 0; i < 4; i++)
#pragma unroll
        for (int j = 0; j < 4; j++) acc[i][j] = 0.f;

    for (int kc = 0; kc < IN_CH; kc += GK) {
#pragma unroll
        for (int i = 0; i < 4; i++) {
            int slot = tid + i * 256;           // 0..1023 float4 slots
            int r = slot >> 4;                  // row 0..63
            int kq = slot & 15;                 // float4 idx within 64 k
            int grow = row0 + r;
            float4 v = make_float4(0.f, 0.f, 0.f, 0.f);
            if (grow < N_NODES)
                v = *(const float4*)&x[(long long)grow * IN_CH + kc + kq * 4];
            XsT[kq * 4 + 0][r] = v.x;
            XsT[kq * 4 + 1][r] = v.y;
            XsT[kq * 4 + 2][r] = v.z;
            XsT[kq * 4 + 3][r] = v.w;
        }
#pragma unroll
        for (int i = 0; i < 4; i++) {
            int slot = tid + i * 256;
            int k = slot >> 4;
            int nq = slot & 15;
            *(float4*)&Ws[k][nq * 4] =
                *(const float4*)&g_Wc[(kc + k) * OUT_CH + nq * 4];
        }
        __syncthreads();
#pragma unroll
        for (int k = 0; k < GK; k++) {
            float4 a = *(const float4*)&XsT[k][ty * 4];
            float4 b = *(const float4*)&Ws[k][tx * 4];
            float ar[4] = {a.x, a.y, a.z, a.w};
            float br[4] = {b.x, b.y, b.z, b.w};
#pragma unroll
            for (int i = 0; i < 4; i++)
#pragma unroll
                for (int j = 0; j < 4; j++) acc[i][j] += ar[i] * br[j];
        }
        __syncthreads();
    }
#pragma unroll
    for (int i = 0; i < 4; i++) {
        int grow = row0 + ty * 4 + i;
        if (grow < N_NODES) {
            __half2 p[2];
            p[0] = __floats2half2_rn(acc[i][0], acc[i][1]);
            p[1] = __floats2half2_rn(acc[i][2], acc[i][3]);
            *(uint2*)&g_t[(size_t)grow * OUT_CH + tx * 4] = *(uint2*)p;
        }
    }
}

// ---------------- CSR aggregation (fp16 gather, fp32 accumulate) ----------------
// phase 0: g_t -> g_y ; phase 1: g_y -> g_t ; phase 2: g_t -> out_final (fp32)
// 8 threads per node, each owns 8 halves (one uint4 = 16B per gather).
__global__ __launch_bounds__(256) void k_agg(int phase, float* __restrict__ out_final) {
    const __half* __restrict__ in = (phase == 1) ? g_y : g_t;
    __half* __restrict__ outh = (phase == 0) ? g_y : g_t;

    int tid = blockIdx.x * blockDim.x + threadIdx.x;
    int node = tid >> 3;
    int l = tid & 7;
    if (node >= N_NODES) return;
    int s = g_off[node];
    int e = g_off[node + 1];
    float acc[8];
#pragma unroll
    for (int q = 0; q < 8; q++) acc[q] = 0.f;

    int i = s;
    for (; i + 4 <= e; i += 4) {
        int c0 = __ldg(&g_col[i]);
        int c1 = __ldg(&g_col[i + 1]);
        int c2 = __ldg(&g_col[i + 2]);
        int c3 = __ldg(&g_col[i + 3]);
        uint4 u0 = *(const uint4*)&in[(size_t)c0 * OUT_CH + l * 8];
        uint4 u1 = *(const uint4*)&in[(size_t)c1 * OUT_CH + l * 8];
        uint4 u2 = *(const uint4*)&in[(size_t)c2 * OUT_CH + l * 8];
        uint4 u3 = *(const uint4*)&in[(size_t)c3 * OUT_CH + l * 8];
        const __half2* h0 = (const __half2*)&u0;
        const __half2* h1 = (const __half2*)&u1;
        const __half2* h2 = (const __half2*)&u2;
        const __half2* h3 = (const __half2*)&u3;
#pragma unroll
        for (int q = 0; q < 4; q++) {
            float2 f0 = __half22float2(h0[q]);
            float2 f1 = __half22float2(h1[q]);
            float2 f2 = __half22float2(h2[q]);
            float2 f3 = __half22float2(h3[q]);
            acc[2 * q + 0] += (f0.x + f1.x) + (f2.x + f3.x);
            acc[2 * q + 1] += (f0.y + f1.y) + (f2.y + f3.y);
        }
    }
    for (; i < e; i++) {
        int c = __ldg(&g_col[i]);
        uint4 u = *(const uint4*)&in[(size_t)c * OUT_CH + l * 8];
        const __half2* h = (const __half2*)&u;
#pragma unroll
        for (int q = 0; q < 4; q++) {
            float2 f = __half22float2(h[q]);
            acc[2 * q + 0] += f.x;
            acc[2 * q + 1] += f.y;
        }
    }

    if (phase < 2) {
        __half2 p[4];
#pragma unroll
        for (int q = 0; q < 4; q++)
            p[q] = __floats2half2_rn(acc[2 * q], acc[2 * q + 1]);
        *(uint4*)&outh[(size_t)node * OUT_CH + l * 8] = *(uint4*)p;
    } else {
        float4 o0 = make_float4(acc[0], acc[1], acc[2], acc[3]);
        float4 o1 = make_float4(acc[4], acc[5], acc[6], acc[7]);
        *(float4*)&out_final[(size_t)node * OUT_CH + l * 8] = o0;
        *(float4*)&out_final[(size_t)node * OUT_CH + l * 8 + 4] = o1;
    }
}

// ---------------- launch ----------------
extern "C" void kernel_launch(void* const* d_in, const int* in_sizes, int n_in,
                              void* d_out, int out_size) {
    const float* x  = (const float*)d_in[0];
    const void*  ei = d_in[1];
    const float* W1 = (const float*)d_in[2];
    const float* W2 = (const float*)d_in[3];
    const float* W3 = (const float*)d_in[4];
    float* out = (float*)d_out;

    const int EB = (N_EDGES + 255) / 256;            // 6250
    const int GB = (N_NODES + GM - 1) / GM;          // 1563
    const int AB = (N_NODES * 8 + 255) / 256;        // 3125

    k_detect<<<1, 32>>>((const int*)ei);
    k_convert<<<2048, 256>>>(ei);
    k_hist<<<EB, 256>>>();
    k_scan1<<<SB, SCAN_T>>>();
    k_scan2<<<1, 256>>>();
    k_scan3<<<SB, SCAN_T>>>();
    k_fill<<<EB, 256>>>();

    k_w1w2<<<IN_CH, IN_CH>>>(W1, W2);
    k_wc<<<IN_CH, OUT_CH>>>(W3);
    k_gemm<<<GB, 256>>>(x);

    k_agg<<<AB, 256>>>(0, out);
    k_agg<<<AB, 256>>>(1, out);
    k_agg<<<AB, 256>>>(2, out);
}

// round 6
// speedup vs baseline: 1.4875x; 1.1133x over previous
#include <cuda_runtime.h>
#include <cuda_bf16.h>
#include <cuda_fp16.h>

#define N_NODES 100000
#define N_EDGES 1600000
#define IN_CH   128
#define OUT_CH  64
#define SCAN_T  512
#define SB ((N_NODES + SCAN_T - 1) / SCAN_T)   /* 196 */
#define EB ((N_EDGES + 255) / 256)             /* 6250 */

// ---------------- device scratch (static, allocation-free) ----------------
__device__ float  g_Wtmp[IN_CH * IN_CH];     // W1@W2  [128,128]
__device__ float  g_Wc[IN_CH * OUT_CH];      // W1@W2@W3 [128,64]
__device__ int    g_src[N_EDGES];
__device__ int    g_dst[N_EDGES];
__device__ int    g_col[N_EDGES];            // src ids grouped by dst (CSR cols)
__device__ int    g_off[N_NODES + 1];        // CSR row offsets
__device__ int    g_cnt[N_NODES];            // histogram, then cursor
__device__ int    g_bsum[256];               // scan block partials
__device__ __half g_t[N_NODES * OUT_CH];     // ping (fp16 features)
__device__ __half g_y[N_NODES * OUT_CH];     // pong (fp16 features)
__device__ int    g_is64;

// ---------------- zero histogram + dtype detect (fused) ----------------
__global__ void k_detect_zero(const int* ei) {
    int idx = blockIdx.x * blockDim.x + threadIdx.x;
    if (idx < N_NODES) g_cnt[idx] = 0;
    if (idx == 0) {
        int is64 = 1;
        for (int i = 0; i < 64; i++) {
            if (ei[2 * i + 1] != 0) { is64 = 0; break; }
        }
        g_is64 = is64;
    }
}

// ---------------- convert edge_index -> int32 + histogram (fused) ----------
__global__ void k_convert_hist(const void* ei) {
    int is64 = g_is64;
    int tid = blockIdx.x * blockDim.x + threadIdx.x;
    int stride = gridDim.x * blockDim.x;
    for (int e = tid; e < N_EDGES; e += stride) {
        int s, d;
        if (is64) {
            const long long* p = (const long long*)ei;
            s = (int)p[e];
            d = (int)p[(long long)N_EDGES + e];
        } else {
            const int* p = (const int*)ei;
            s = p[e];
            d = p[N_EDGES + e];
        }
        g_src[e] = s;
        g_dst[e] = d;
        atomicAdd(&g_cnt[d], 1);
    }
}

// ---------------- exclusive scan ----------------
__global__ void k_scan1() {
    __shared__ int s[SCAN_T];
    int t = threadIdx.x;
    int idx = blockIdx.x * SCAN_T + t;
    int v = (idx < N_NODES) ? g_cnt[idx] : 0;
    s[t] = v;
    __syncthreads();
    for (int o = 1; o < SCAN_T; o <<= 1) {
        int add = (t >= o) ? s[t - o] : 0;
        __syncthreads();
        s[t] += add;
        __syncthreads();
    }
    if (idx < N_NODES) g_off[idx] = s[t] - v;   // exclusive (local)
    if (t == SCAN_T - 1) g_bsum[blockIdx.x] = s[t];
}

// one block scans the 196 block partials in smem
__global__ void k_scan2() {
    __shared__ int s[256];
    int t = threadIdx.x;
    int v = (t < SB) ? g_bsum[t] : 0;
    s[t] = v;
    __syncthreads();
    for (int o = 1; o < 256; o <<= 1) {
        int a = (t >= o) ? s[t - o] : 0;
        __syncthreads();
        s[t] += a;
        __syncthreads();
    }
    if (t < SB) g_bsum[t] = s[t] - v;   // exclusive prefix of block sums
}

// finalize offsets + init fill cursors (fused)
__global__ void k_scan3() {
    int idx = blockIdx.x * SCAN_T + threadIdx.x;
    if (idx < N_NODES) {
        int v = g_off[idx] + g_bsum[blockIdx.x];
        g_off[idx] = v;
        g_cnt[idx] = v;
    }
    if (idx == 0) g_off[N_NODES] = N_EDGES;
}

__global__ void k_fill() {
    int e = blockIdx.x * blockDim.x + threadIdx.x;
    if (e < N_EDGES) {
        int d = g_dst[e];
        int p = atomicAdd(&g_cnt[d], 1);
        g_col[p] = g_src[e];
    }
}

// ---------------- weight chain: Wtmp = W1@W2 ; Wc = Wtmp@W3 ----------------
__global__ void k_w1w2(const float* __restrict__ W1, const float* __restrict__ W2) {
    int k = blockIdx.x;      // 0..127
    int j = threadIdx.x;     // 0..127
    float s = 0.f;
#pragma unroll 8
    for (int m = 0; m < IN_CH; m++)
        s += W1[k * IN_CH + m] * W2[m * IN_CH + j];
    g_Wtmp[k * IN_CH + j] = s;
}
__global__ void k_wc(const float* __restrict__ W3) {
    int k = blockIdx.x;      // 0..127
    int j = threadIdx.x;     // 0..63
    float s = 0.f;
#pragma unroll 8
    for (int m = 0; m < IN_CH; m++)
        s += g_Wtmp[k * IN_CH + m] * W3[m * OUT_CH + j];
    g_Wc[k * OUT_CH + j] = s;
}

// ---------------- GEMM: t[100000,64] = x[100000,128] @ Wc[128,64] (fp16 out) --
#define GM 64
#define GK 64
__global__ __launch_bounds__(256) void k_gemm(const float* __restrict__ x) {
    __shared__ float XsT[GK][GM + 4];   // transposed: [k][row]
    __shared__ float Ws[GK][OUT_CH];    // [k][col]
    int row0 = blockIdx.x * GM;
    int tid = threadIdx.x;
    int ty = tid >> 4;        // 0..15 -> rows ty*4..+3
    int tx = tid & 15;        // 0..15 -> cols tx*4..+3
    float acc[4][4];
#pragma unroll
    for (int i = 0; i < 4; i++)
#pragma unroll
        for (int j = 0; j < 4; j++) acc[i][j] = 0.f;

    for (int kc = 0; kc < IN_CH; kc += GK) {
#pragma unroll
        for (int i = 0; i < 4; i++) {
            int slot = tid + i * 256;           // 0..1023 float4 slots
            int r = slot >> 4;                  // row 0..63
            int kq = slot & 15;                 // float4 idx within 64 k
            int grow = row0 + r;
            float4 v = make_float4(0.f, 0.f, 0.f, 0.f);
            if (grow < N_NODES)
                v = *(const float4*)&x[(long long)grow * IN_CH + kc + kq * 4];
            XsT[kq * 4 + 0][r] = v.x;
            XsT[kq * 4 + 1][r] = v.y;
            XsT[kq * 4 + 2][r] = v.z;
            XsT[kq * 4 + 3][r] = v.w;
        }
#pragma unroll
        for (int i = 0; i < 4; i++) {
            int slot = tid + i * 256;
            int k = slot >> 4;
            int nq = slot & 15;
            *(float4*)&Ws[k][nq * 4] =
                *(const float4*)&g_Wc[(kc + k) * OUT_CH + nq * 4];
        }
        __syncthreads();
#pragma unroll
        for (int k = 0; k < GK; k++) {
            float4 a = *(const float4*)&XsT[k][ty * 4];
            float4 b = *(const float4*)&Ws[k][tx * 4];
            float ar[4] = {a.x, a.y, a.z, a.w};
            float br[4] = {b.x, b.y, b.z, b.w};
#pragma unroll
            for (int i = 0; i < 4; i++)
#pragma unroll
                for (int j = 0; j < 4; j++) acc[i][j] += ar[i] * br[j];
        }
        __syncthreads();
    }
#pragma unroll
    for (int i = 0; i < 4; i++) {
        int grow = row0 + ty * 4 + i;
        if (grow < N_NODES) {
            __half2 p[2];
            p[0] = __floats2half2_rn(acc[i][0], acc[i][1]);
            p[1] = __floats2half2_rn(acc[i][2], acc[i][3]);
            *(uint2*)&g_t[(size_t)grow * OUT_CH + tx * 4] = *(uint2*)p;
        }
    }
}

// ---------------- CSR aggregation (fp16 gather, fp32 accumulate) ----------------
__global__ __launch_bounds__(256) void k_agg(int phase, float* __restrict__ out_final) {
    const __half* __restrict__ in = (phase == 1) ? g_y : g_t;
    __half* __restrict__ outh = (phase == 0) ? g_y : g_t;

    int tid = blockIdx.x * blockDim.x + threadIdx.x;
    int node = tid >> 3;
    int l = tid & 7;
    if (node >= N_NODES) return;
    int s = g_off[node];
    int e = g_off[node + 1];
    float acc[8];
#pragma unroll
    for (int q = 0; q < 8; q++) acc[q] = 0.f;

    int i = s;
    for (; i + 4 <= e; i += 4) {
        int c0 = __ldg(&g_col[i]);
        int c1 = __ldg(&g_col[i + 1]);
        int c2 = __ldg(&g_col[i + 2]);
        int c3 = __ldg(&g_col[i + 3]);
        uint4 u0 = *(const uint4*)&in[(size_t)c0 * OUT_CH + l * 8];
        uint4 u1 = *(const uint4*)&in[(size_t)c1 * OUT_CH + l * 8];
        uint4 u2 = *(const uint4*)&in[(size_t)c2 * OUT_CH + l * 8];
        uint4 u3 = *(const uint4*)&in[(size_t)c3 * OUT_CH + l * 8];
        const __half2* h0 = (const __half2*)&u0;
        const __half2* h1 = (const __half2*)&u1;
        const __half2* h2 = (const __half2*)&u2;
        const __half2* h3 = (const __half2*)&u3;
#pragma unroll
        for (int q = 0; q < 4; q++) {
            float2 f0 = __half22float2(h0[q]);
            float2 f1 = __half22float2(h1[q]);
            float2 f2 = __half22float2(h2[q]);
            float2 f3 = __half22float2(h3[q]);
            acc[2 * q + 0] += (f0.x + f1.x) + (f2.x + f3.x);
            acc[2 * q + 1] += (f0.y + f1.y) + (f2.y + f3.y);
        }
    }
    for (; i < e; i++) {
        int c = __ldg(&g_col[i]);
        uint4 u = *(const uint4*)&in[(size_t)c * OUT_CH + l * 8];
        const __half2* h = (const __half2*)&u;
#pragma unroll
        for (int q = 0; q < 4; q++) {
            float2 f = __half22float2(h[q]);
            acc[2 * q + 0] += f.x;
            acc[2 * q + 1] += f.y;
        }
    }

    if (phase < 2) {
        __half2 p[4];
#pragma unroll
        for (int q = 0; q < 4; q++)
            p[q] = __floats2half2_rn(acc[2 * q], acc[2 * q + 1]);
        *(uint4*)&outh[(size_t)node * OUT_CH + l * 8] = *(uint4*)p;
    } else {
        float4 o0 = make_float4(acc[0], acc[1], acc[2], acc[3]);
        float4 o1 = make_float4(acc[4], acc[5], acc[6], acc[7]);
        *(float4*)&out_final[(size_t)node * OUT_CH + l * 8] = o0;
        *(float4*)&out_final[(size_t)node * OUT_CH + l * 8 + 4] = o1;
    }
}

// ---------------- launch: two concurrent chains inside the captured graph ----
extern "C" void kernel_launch(void* const* d_in, const int* in_sizes, int n_in,
                              void* d_out, int out_size) {
    const float* x  = (const float*)d_in[0];
    const void*  ei = d_in[1];
    const float* W1 = (const float*)d_in[2];
    const float* W2 = (const float*)d_in[3];
    const float* W3 = (const float*)d_in[4];
    float* out = (float*)d_out;

    const int ZB = (N_NODES + 1023) / 1024;          // 98
    const int GB = (N_NODES + GM - 1) / GM;          // 1563
    const int AB = (N_NODES * 8 + 255) / 256;        // 3125

    cudaStream_t s2;
    cudaStreamCreateWithFlags(&s2, cudaStreamNonBlocking);
    cudaEvent_t evF, evJ;
    cudaEventCreateWithFlags(&evF, cudaEventDisableTiming);
    cudaEventCreateWithFlags(&evJ, cudaEventDisableTiming);

    // fork: s2 branches off the capture (default) stream at the start
    cudaEventRecord(evF, 0);
    cudaStreamWaitEvent(s2, evF, 0);

    // ---- chain B on s2: weight chain + GEMM (independent of edges) ----
    k_w1w2<<<IN_CH, IN_CH, 0, s2>>>(W1, W2);
    k_wc<<<IN_CH, OUT_CH, 0, s2>>>(W3);
    k_gemm<<<GB, 256, 0, s2>>>(x);
    cudaEventRecord(evJ, s2);

    // ---- chain A on default stream: CSR build ----
    k_detect_zero<<<ZB, 1024>>>((const int*)ei);
    k_convert_hist<<<2048, 256>>>(ei);
    k_scan1<<<SB, SCAN_T>>>();
    k_scan2<<<1, 256>>>();
    k_scan3<<<SB, SCAN_T>>>();
    k_fill<<<EB, 256>>>();

    // join: agg needs both chains done
    cudaStreamWaitEvent(0, evJ, 0);

    k_agg<<<AB, 256>>>(0, out);
    k_agg<<<AB, 256>>>(1, out);
    k_agg<<<AB, 256>>>(2, out);

    cudaEventDestroy(evF);
    cudaEventDestroy(evJ);
    cudaStreamDestroy(s2);
}

// round 8
// speedup vs baseline: 1.5041x; 1.0111x over previous
#include <cuda_runtime.h>
#include <cuda_bf16.h>
#include <cuda_fp16.h>

#define N_NODES 100000
#define N_EDGES 1600000
#define IN_CH   128
#define OUT_CH  64
#define SCAN_T  512
#define SB ((N_NODES + SCAN_T - 1) / SCAN_T)   /* 196 */
#define EB ((N_EDGES + 255) / 256)             /* 6250 */

// ---------------- device scratch (static, allocation-free) ----------------
// g_cnt is ZERO at every kernel_launch entry: zero-initialized at module load
// (first call), and k_clear re-zeroes it at the end of every call (overlapped
// with the agg passes on stream s2, joined before capture ends).
__device__ float  g_Wtmp[IN_CH * IN_CH];     // W1@W2  [128,128]
__device__ float  g_Wc[IN_CH * OUT_CH];      // W1@W2@W3 [128,64]
__device__ int    g_src[N_EDGES];
__device__ int    g_dst[N_EDGES];
__device__ int    g_rank[N_EDGES];           // rank of edge within its dst bucket
__device__ int    g_col[N_EDGES];            // src ids grouped by dst (CSR cols)
__device__ int    g_off[N_NODES + 1];        // CSR row offsets
__device__ int    g_cnt[N_NODES];            // histogram (zeroed at end of call)
__device__ int    g_bsum[256];               // scan block partials
__device__ __half g_t[N_NODES * OUT_CH];     // ping (fp16 features)
__device__ __half g_y[N_NODES * OUT_CH];     // pong (fp16 features)

// ---------------- convert + histogram + rank (fused; inline dtype detect) ----
__global__ void k_convert(const void* ei) {
    // int64 input => odd 32-bit words of first elements are high words == 0
    // (all ids < 100000). int32 input => they are real src values (P(all 0)~1e-20).
    const int* w = (const int*)ei;
    bool is64 = ((w[1] | w[3] | w[5] | w[7]) == 0);
    int tid = blockIdx.x * blockDim.x + threadIdx.x;
    int stride = gridDim.x * blockDim.x;
    for (int e = tid; e < N_EDGES; e += stride) {
        int s, d;
        if (is64) {
            const long long* p = (const long long*)ei;
            s = (int)p[e];
            d = (int)p[(long long)N_EDGES + e];
        } else {
            const int* p = (const int*)ei;
            s = p[e];
            d = p[N_EDGES + e];
        }
        g_src[e] = s;
        g_dst[e] = d;
        g_rank[e] = atomicAdd(&g_cnt[d], 1);   // histogram + bucket rank in one
    }
}

// ---------------- exclusive scan over g_cnt -> g_off ----------------
__global__ void k_scan1() {
    __shared__ int s[SCAN_T];
    int t = threadIdx.x;
    int idx = blockIdx.x * SCAN_T + t;
    int v = (idx < N_NODES) ? g_cnt[idx] : 0;
    s[t] = v;
    __syncthreads();
    for (int o = 1; o < SCAN_T; o <<= 1) {
        int add = (t >= o) ? s[t - o] : 0;
        __syncthreads();
        s[t] += add;
        __syncthreads();
    }
    if (idx < N_NODES) g_off[idx] = s[t] - v;   // exclusive (local)
    if (t == SCAN_T - 1) g_bsum[blockIdx.x] = s[t];
}

// one block scans the 196 block partials in smem
__global__ void k_scan2() {
    __shared__ int s[256];
    int t = threadIdx.x;
    int v = (t < SB) ? g_bsum[t] : 0;
    s[t] = v;
    __syncthreads();
    for (int o = 1; o < 256; o <<= 1) {
        int a = (t >= o) ? s[t - o] : 0;
        __syncthreads();
        s[t] += a;
        __syncthreads();
    }
    if (t < SB) g_bsum[t] = s[t] - v;   // exclusive prefix of block sums
}

// finalize offsets
__global__ void k_scan3() {
    int idx = blockIdx.x * SCAN_T + threadIdx.x;
    if (idx < N_NODES) g_off[idx] += g_bsum[blockIdx.x];
    if (idx == 0) g_off[N_NODES] = N_EDGES;
}

// ---------------- atomic-free CSR fill (uses precomputed ranks) ----------------
__global__ void k_fill() {
    int e = blockIdx.x * blockDim.x + threadIdx.x;
    if (e < N_EDGES) {
        int d = g_dst[e];
        g_col[g_off[d] + g_rank[e]] = g_src[e];
    }
}

// ---------------- end-of-call clear: g_cnt -> 0 for the NEXT call ----------------
__global__ void k_clear() {
    int idx = blockIdx.x * blockDim.x + threadIdx.x;
    if (idx < N_NODES) g_cnt[idx] = 0;
}

// ---------------- weight chain: Wtmp = W1@W2 ; Wc = Wtmp@W3 ----------------
__global__ void k_w1w2(const float* __restrict__ W1, const float* __restrict__ W2) {
    int k = blockIdx.x;      // 0..127
    int j = threadIdx.x;     // 0..127
    float s = 0.f;
#pragma unroll 8
    for (int m = 0; m < IN_CH; m++)
        s += W1[k * IN_CH + m] * W2[m * IN_CH + j];
    g_Wtmp[k * IN_CH + j] = s;
}
__global__ void k_wc(const float* __restrict__ W3) {
    int k = blockIdx.x;      // 0..127
    int j = threadIdx.x;     // 0..63
    float s = 0.f;
#pragma unroll 8
    for (int m = 0; m < IN_CH; m++)
        s += g_Wtmp[k * IN_CH + m] * W3[m * OUT_CH + j];
    g_Wc[k * OUT_CH + j] = s;
}

// ---------------- GEMM: t[100000,64] = x[100000,128] @ Wc[128,64] (fp16 out) --
#define GM 64
#define GK 64
__global__ __launch_bounds__(256) void k_gemm(const float* __restrict__ x) {
    __shared__ float XsT[GK][GM + 4];   // transposed: [k][row]
    __shared__ float Ws[GK][OUT_CH];    // [k][col]
    int row0 = blockIdx.x * GM;
    int tid = threadIdx.x;
    int ty = tid >> 4;        // 0..15 -> rows ty*4..+3
    int tx = tid & 15;        // 0..15 -> cols tx*4..+3
    float acc[4][4];
#pragma unroll
    for (int i = 0; i < 4; i++)
#pragma unroll
        for (int j = 0; j < 4; j++) acc[i][j] = 0.f;

    for (int kc = 0; kc < IN_CH; kc += GK) {
#pragma unroll
        for (int i = 0; i < 4; i++) {
            int slot = tid + i * 256;           // 0..1023 float4 slots
            int r = slot >> 4;                  // row 0..63
            int kq = slot & 15;                 // float4 idx within 64 k
            int grow = row0 + r;
            float4 v = make_float4(0.f, 0.f, 0.f, 0.f);
            if (grow < N_NODES)
                v = *(const float4*)&x[(long long)grow * IN_CH + kc + kq * 4];
            XsT[kq * 4 + 0][r] = v.x;
            XsT[kq * 4 + 1][r] = v.y;
            XsT[kq * 4 + 2][r] = v.z;
            XsT[kq * 4 + 3][r] = v.w;
        }
#pragma unroll
        for (int i = 0; i < 4; i++) {
            int slot = tid + i * 256;
            int k = slot >> 4;
            int nq = slot & 15;
            *(float4*)&Ws[k][nq * 4] =
                *(const float4*)&g_Wc[(kc + k) * OUT_CH + nq * 4];
        }
        __syncthreads();
#pragma unroll
        for (int k = 0; k < GK; k++) {
            float4 a = *(const float4*)&XsT[k][ty * 4];
            float4 b = *(const float4*)&Ws[k][tx * 4];
            float ar[4] = {a.x, a.y, a.z, a.w};
            float br[4] = {b.x, b.y, b.z, b.w};
#pragma unroll
            for (int i = 0; i < 4; i++)
#pragma unroll
                for (int j = 0; j < 4; j++) acc[i][j] += ar[i] * br[j];
        }
        __syncthreads();
    }
#pragma unroll
    for (int i = 0; i < 4; i++) {
        int grow = row0 + ty * 4 + i;
        if (grow < N_NODES) {
            __half2 p[2];
            p[0] = __floats2half2_rn(acc[i][0], acc[i][1]);
            p[1] = __floats2half2_rn(acc[i][2], acc[i][3]);
            *(uint2*)&g_t[(size_t)grow * OUT_CH + tx * 4] = *(uint2*)p;
        }
    }
}

// ---------------- CSR aggregation (fp16 gather, fp32 accumulate) ----------------
__global__ __launch_bounds__(256) void k_agg(int phase, float* __restrict__ out_final) {
    const __half* __restrict__ in = (phase == 1) ? g_y : g_t;
    __half* __restrict__ outh = (phase == 0) ? g_y : g_t;

    int tid = blockIdx.x * blockDim.x + threadIdx.x;
    int node = tid >> 3;
    int l = tid & 7;
    if (node >= N_NODES) return;
    int s = g_off[node];
    int e = g_off[node + 1];
    float acc[8];
#pragma unroll
    for (int q = 0; q < 8; q++) acc[q] = 0.f;

    int i = s;
    for (; i + 4 <= e; i += 4) {
        int c0 = __ldg(&g_col[i]);
        int c1 = __ldg(&g_col[i + 1]);
        int c2 = __ldg(&g_col[i + 2]);
        int c3 = __ldg(&g_col[i + 3]);
        uint4 u0 = *(const uint4*)&in[(size_t)c0 * OUT_CH + l * 8];
        uint4 u1 = *(const uint4*)&in[(size_t)c1 * OUT_CH + l * 8];
        uint4 u2 = *(const uint4*)&in[(size_t)c2 * OUT_CH + l * 8];
        uint4 u3 = *(const uint4*)&in[(size_t)c3 * OUT_CH + l * 8];
        const __half2* h0 = (const __half2*)&u0;
        const __half2* h1 = (const __half2*)&u1;
        const __half2* h2 = (const __half2*)&u2;
        const __half2* h3 = (const __half2*)&u3;
#pragma unroll
        for (int q = 0; q < 4; q++) {
            float2 f0 = __half22float2(h0[q]);
            float2 f1 = __half22float2(h1[q]);
            float2 f2 = __half22float2(h2[q]);
            float2 f3 = __half22float2(h3[q]);
            acc[2 * q + 0] += (f0.x + f1.x) + (f2.x + f3.x);
            acc[2 * q + 1] += (f0.y + f1.y) + (f2.y + f3.y);
        }
    }
    for (; i < e; i++) {
        int c = __ldg(&g_col[i]);
        uint4 u = *(const uint4*)&in[(size_t)c * OUT_CH + l * 8];
        const __half2* h = (const __half2*)&u;
#pragma unroll
        for (int q = 0; q < 4; q++) {
            float2 f = __half22float2(h[q]);
            acc[2 * q + 0] += f.x;
            acc[2 * q + 1] += f.y;
        }
    }

    if (phase < 2) {
        __half2 p[4];
#pragma unroll
        for (int q = 0; q < 4; q++)
            p[q] = __floats2half2_rn(acc[2 * q], acc[2 * q + 1]);
        *(uint4*)&outh[(size_t)node * OUT_CH + l * 8] = *(uint4*)p;
    } else {
        float4 o0 = make_float4(acc[0], acc[1], acc[2], acc[3]);
        float4 o1 = make_float4(acc[4], acc[5], acc[6], acc[7]);
        *(float4*)&out_final[(size_t)node * OUT_CH + l * 8] = o0;
        *(float4*)&out_final[(size_t)node * OUT_CH + l * 8 + 4] = o1;
    }
}

// ---------------- launch: two concurrent chains inside the captured graph ----
extern "C" void kernel_launch(void* const* d_in, const int* in_sizes, int n_in,
                              void* d_out, int out_size) {
    const float* x  = (const float*)d_in[0];
    const void*  ei = d_in[1];
    const float* W1 = (const float*)d_in[2];
    const float* W2 = (const float*)d_in[3];
    const float* W3 = (const float*)d_in[4];
    float* out = (float*)d_out;

    const int ZB = (N_NODES + 1023) / 1024;          // 98
    const int GB = (N_NODES + GM - 1) / GM;          // 1563
    const int AB = (N_NODES * 8 + 255) / 256;        // 3125

    cudaStream_t s2;
    cudaStreamCreateWithFlags(&s2, cudaStreamNonBlocking);
    cudaEvent_t evF, evJ, evS1, evC;
    cudaEventCreateWithFlags(&evF,  cudaEventDisableTiming);
    cudaEventCreateWithFlags(&evJ,  cudaEventDisableTiming);
    cudaEventCreateWithFlags(&evS1, cudaEventDisableTiming);
    cudaEventCreateWithFlags(&evC,  cudaEventDisableTiming);

    // fork: s2 branches off the capture (default) stream at the start
    cudaEventRecord(evF, 0);
    cudaStreamWaitEvent(s2, evF, 0);

    // ---- chain B on s2: weight chain + GEMM (independent of edges) ----
    k_w1w2<<<IN_CH, IN_CH, 0, s2>>>(W1, W2);
    k_wc<<<IN_CH, OUT_CH, 0, s2>>>(W3);
    k_gemm<<<GB, 256, 0, s2>>>(x);
    cudaEventRecord(evJ, s2);

    // ---- chain A on default stream: CSR build ----
    k_convert<<<2048, 256>>>(ei);       // convert + hist + rank (g_cnt pre-zeroed)
    k_scan1<<<SB, SCAN_T>>>();
    cudaEventRecord(evS1, 0);           // last reader of g_cnt done
    k_scan2<<<1, 256>>>();
    k_scan3<<<SB, SCAN_T>>>();
    k_fill<<<EB, 256>>>();              // atomic-free scatter via ranks

    // clear g_cnt for the NEXT call, on s2, after scan1 (last g_cnt reader)
    // and after chain B's tail (keeps s2 linear: ...gemm -> clear).
    cudaStreamWaitEvent(s2, evS1, 0);
    k_clear<<<ZB, 1024, 0, s2>>>();
    cudaEventRecord(evC, s2);           // s2 branch tail

    // join 1: agg needs g_t (chain B done before clear, covered by evC too)
    cudaStreamWaitEvent(0, evJ, 0);

    k_agg<<<AB, 256>>>(0, out);
    k_agg<<<AB, 256>>>(1, out);
    k_agg<<<AB, 256>>>(2, out);

    // join 2: fold the s2 tail (k_clear) back into the origin stream so the
    // capture has no unjoined work. Placed after agg so the clear overlaps them.
    cudaStreamWaitEvent(0, evC, 0);

    cudaEventDestroy(evF);
    cudaEventDestroy(evJ);
    cudaEventDestroy(evS1);
    cudaEventDestroy(evC);
    cudaStreamDestroy(s2);
}

// round 9
// speedup vs baseline: 1.5620x; 1.0385x over previous
#include <cuda_runtime.h>
#include <cuda_bf16.h>
#include <cuda_fp16.h>

#define N_NODES 100000
#define N_EDGES 1600000
#define IN_CH   128
#define OUT_CH  64
#define SCAN_T  512
#define SB ((N_NODES + SCAN_T - 1) / SCAN_T)   /* 196 */
#define EB ((N_EDGES + 255) / 256)             /* 6250 */

// ---------------- device scratch (static, allocation-free) ----------------
// g_cnt and g_state are ZERO at every kernel_launch entry: zero-init at module
// load (first call), k_clear re-zeroes at end of every call (graph replays are
// sequential, so the clear of replay N completes before replay N+1 starts).
__device__ float              g_W23[IN_CH * OUT_CH];   // W2@W3   [128,64]
__device__ float              g_Wc[IN_CH * OUT_CH];    // W1@W23  [128,64]
__device__ int                g_rank[N_EDGES];         // edge rank within dst bucket
__device__ int                g_col[N_EDGES];          // src ids grouped by dst
__device__ int                g_off[N_NODES + 1];      // CSR row offsets
__device__ int                g_cnt[N_NODES];          // histogram (cleared per call)
__device__ unsigned long long g_state[SB];             // lookback: (flag<<32)|value
__device__ __half             g_t[N_NODES * OUT_CH];   // ping (fp16 features)
__device__ __half             g_y[N_NODES * OUT_CH];   // pong (fp16 features)

// ---------------- convert: dst-half only -> histogram + rank ----------------
__global__ void k_convert(const void* ei) {
    // int64 => odd 32-bit words are high words == 0 (ids < 100000).
    // int32 => they are real src values (P(first 4 all zero) ~ 1e-20).
    const int* w = (const int*)ei;
    bool is64 = ((w[1] | w[3] | w[5] | w[7]) == 0);
    int tid = blockIdx.x * blockDim.x + threadIdx.x;
    int stride = gridDim.x * blockDim.x;
    for (int e = tid; e < N_EDGES; e += stride) {
        int d;
        if (is64) d = (int)((const long long*)ei)[(long long)N_EDGES + e];
        else      d = ((const int*)ei)[N_EDGES + e];
        g_rank[e] = atomicAdd(&g_cnt[d], 1);   // histogram + bucket rank in one
    }
}

// ---------------- single-pass scan: decoupled lookback ----------------
// grid = SB (196 blocks, all co-resident: 196 < 148*4), block = 512.
__global__ void k_scan() {
    __shared__ int s[SCAN_T];
    __shared__ int sh_excl;
    int t = threadIdx.x, b = blockIdx.x;
    int idx = b * SCAN_T + t;
    int v = (idx < N_NODES) ? g_cnt[idx] : 0;
    s[t] = v;
    __syncthreads();
    for (int o = 1; o < SCAN_T; o <<= 1) {
        int a = (t >= o) ? s[t - o] : 0;
        __syncthreads();
        s[t] += a;
        __syncthreads();
    }
    int incl = s[t];
    int total = s[SCAN_T - 1];

    // publish aggregate (block 0 publishes inclusive prefix directly)
    if (t == 0) {
        unsigned long long st = (b == 0)
            ? ((2ULL << 32) | (unsigned long long)(unsigned)total)
            : ((1ULL << 32) | (unsigned long long)(unsigned)total);
        atomicExch(&g_state[b], st);
    }

    if (b == 0) {
        if (t == 0) sh_excl = 0;
    } else if (t < 32) {
        // warp-parallel lookback: lane t inspects predecessor b-1-t, b-33-t, ...
        int excl = 0;
        int p = b - 1;
        while (true) {
            int pi = p - t;
            unsigned long long stv;
            if (pi >= 0) {
                do { stv = atomicAdd(&g_state[pi], 0ULL); } while ((stv >> 32) == 0);
            } else {
                stv = (2ULL << 32);   // virtual zero prefix before block 0
            }
            unsigned flag = (unsigned)(stv >> 32);
            int val = (int)(unsigned)(stv & 0xffffffffULL);
            unsigned done_mask = __ballot_sync(0xffffffffu, flag == 2);
            int k = done_mask ? (__ffs(done_mask) - 1) : 31;
            int contrib = (t <= k) ? val : 0;
#pragma unroll
            for (int o = 16; o > 0; o >>= 1)
                contrib += __shfl_down_sync(0xffffffffu, contrib, o);
            if (t == 0) excl += contrib;
            if (done_mask) break;
            p -= 32;
        }
        if (t == 0) {
            // publish inclusive prefix ASAP to unblock successors
            atomicExch(&g_state[b],
                       (2ULL << 32) | (unsigned long long)(unsigned)(excl + total));
            sh_excl = excl;
        }
    }
    __syncthreads();
    int e0 = sh_excl;
    if (idx < N_NODES) g_off[idx] = e0 + incl - v;   // exclusive scan value
    if (b == 0 && t == 0) g_off[N_NODES] = N_EDGES;
}

// ---------------- atomic-free CSR fill (re-reads ei, uses ranks) ----------------
__global__ void k_fill(const void* ei) {
    const int* w = (const int*)ei;
    bool is64 = ((w[1] | w[3] | w[5] | w[7]) == 0);
    int e = blockIdx.x * blockDim.x + threadIdx.x;
    if (e < N_EDGES) {
        int s, d;
        if (is64) {
            const long long* p = (const long long*)ei;
            s = (int)p[e];
            d = (int)p[(long long)N_EDGES + e];
        } else {
            const int* p = (const int*)ei;
            s = p[e];
            d = p[N_EDGES + e];
        }
        g_col[g_off[d] + g_rank[e]] = s;
    }
}

// ---------------- end-of-call clear: g_cnt + g_state -> 0 for NEXT call --------
__global__ void k_clear() {
    int idx = blockIdx.x * blockDim.x + threadIdx.x;
    if (idx < N_NODES) g_cnt[idx] = 0;
    if (idx < SB) g_state[idx] = 0ULL;
}

// ---------------- weight chain: W23 = W2@W3 ; Wc = W1@W23 ----------------
__global__ void k_w23(const float* __restrict__ W2, const float* __restrict__ W3) {
    int k = blockIdx.x;      // 0..127
    int j = threadIdx.x;     // 0..63
    float s = 0.f;
#pragma unroll 8
    for (int m = 0; m < IN_CH; m++)
        s += W2[k * IN_CH + m] * W3[m * OUT_CH + j];
    g_W23[k * OUT_CH + j] = s;
}
__global__ void k_wc(const float* __restrict__ W1) {
    int k = blockIdx.x;      // 0..127
    int j = threadIdx.x;     // 0..63
    float s = 0.f;
#pragma unroll 8
    for (int m = 0; m < IN_CH; m++)
        s += W1[k * IN_CH + m] * g_W23[m * OUT_CH + j];
    g_Wc[k * OUT_CH + j] = s;
}

// ---------------- GEMM: t[100000,64] = x[100000,128] @ Wc[128,64] (fp16 out) --
#define GM 64
#define GK 64
__global__ __launch_bounds__(256) void k_gemm(const float* __restrict__ x) {
    __shared__ float XsT[GK][GM + 4];   // transposed: [k][row]
    __shared__ float Ws[GK][OUT_CH];    // [k][col]
    int row0 = blockIdx.x * GM;
    int tid = threadIdx.x;
    int ty = tid >> 4;        // 0..15 -> rows ty*4..+3
    int tx = tid & 15;        // 0..15 -> cols tx*4..+3
    float acc[4][4];
#pragma unroll
    for (int i = 0; i < 4; i++)
#pragma unroll
        for (int j = 0; j < 4; j++) acc[i][j] = 0.f;

    for (int kc = 0; kc < IN_CH; kc += GK) {
#pragma unroll
        for (int i = 0; i < 4; i++) {
            int slot = tid + i * 256;           // 0..1023 float4 slots
            int r = slot >> 4;                  // row 0..63
            int kq = slot & 15;                 // float4 idx within 64 k
            int grow = row0 + r;
            float4 v = make_float4(0.f, 0.f, 0.f, 0.f);
            if (grow < N_NODES)
                v = *(const float4*)&x[(long long)grow * IN_CH + kc + kq * 4];
            XsT[kq * 4 + 0][r] = v.x;
            XsT[kq * 4 + 1][r] = v.y;
            XsT[kq * 4 + 2][r] = v.z;
            XsT[kq * 4 + 3][r] = v.w;
        }
#pragma unroll
        for (int i = 0; i < 4; i++) {
            int slot = tid + i * 256;
            int k = slot >> 4;
            int nq = slot & 15;
            *(float4*)&Ws[k][nq * 4] =
                *(const float4*)&g_Wc[(kc + k) * OUT_CH + nq * 4];
        }
        __syncthreads();
#pragma unroll
        for (int k = 0; k < GK; k++) {
            float4 a = *(const float4*)&XsT[k][ty * 4];
            float4 b = *(const float4*)&Ws[k][tx * 4];
            float ar[4] = {a.x, a.y, a.z, a.w};
            float br[4] = {b.x, b.y, b.z, b.w};
#pragma unroll
            for (int i = 0; i < 4; i++)
#pragma unroll
                for (int j = 0; j < 4; j++) acc[i][j] += ar[i] * br[j];
        }
        __syncthreads();
    }
#pragma unroll
    for (int i = 0; i < 4; i++) {
        int grow = row0 + ty * 4 + i;
        if (grow < N_NODES) {
            __half2 p[2];
            p[0] = __floats2half2_rn(acc[i][0], acc[i][1]);
            p[1] = __floats2half2_rn(acc[i][2], acc[i][3]);
            *(uint2*)&g_t[(size_t)grow * OUT_CH + tx * 4] = *(uint2*)p;
        }
    }
}

// ---------------- CSR aggregation (fp16 gather, fp32 accumulate) ----------------
__global__ __launch_bounds__(256) void k_agg(int phase, float* __restrict__ out_final) {
    const __half* __restrict__ in = (phase == 1) ? g_y : g_t;
    __half* __restrict__ outh = (phase == 0) ? g_y : g_t;

    int tid = blockIdx.x * blockDim.x + threadIdx.x;
    int node = tid >> 3;
    int l = tid & 7;
    if (node >= N_NODES) return;
    int s = g_off[node];
    int e = g_off[node + 1];
    float acc[8];
#pragma unroll
    for (int q = 0; q < 8; q++) acc[q] = 0.f;

    int i = s;
    for (; i + 4 <= e; i += 4) {
        int c0 = __ldg(&g_col[i]);
        int c1 = __ldg(&g_col[i + 1]);
        int c2 = __ldg(&g_col[i + 2]);
        int c3 = __ldg(&g_col[i + 3]);
        uint4 u0 = *(const uint4*)&in[(size_t)c0 * OUT_CH + l * 8];
        uint4 u1 = *(const uint4*)&in[(size_t)c1 * OUT_CH + l * 8];
        uint4 u2 = *(const uint4*)&in[(size_t)c2 * OUT_CH + l * 8];
        uint4 u3 = *(const uint4*)&in[(size_t)c3 * OUT_CH + l * 8];
        const __half2* h0 = (const __half2*)&u0;
        const __half2* h1 = (const __half2*)&u1;
        const __half2* h2 = (const __half2*)&u2;
        const __half2* h3 = (const __half2*)&u3;
#pragma unroll
        for (int q = 0; q < 4; q++) {
            float2 f0 = __half22float2(h0[q]);
            float2 f1 = __half22float2(h1[q]);
            float2 f2 = __half22float2(h2[q]);
            float2 f3 = __half22float2(h3[q]);
            acc[2 * q + 0] += (f0.x + f1.x) + (f2.x + f3.x);
            acc[2 * q + 1] += (f0.y + f1.y) + (f2.y + f3.y);
        }
    }
    for (; i < e; i++) {
        int c = __ldg(&g_col[i]);
        uint4 u = *(const uint4*)&in[(size_t)c * OUT_CH + l * 8];
        const __half2* h = (const __half2*)&u;
#pragma unroll
        for (int q = 0; q < 4; q++) {
            float2 f = __half22float2(h[q]);
            acc[2 * q + 0] += f.x;
            acc[2 * q + 1] += f.y;
        }
    }

    if (phase < 2) {
        __half2 p[4];
#pragma unroll
        for (int q = 0; q < 4; q++)
            p[q] = __floats2half2_rn(acc[2 * q], acc[2 * q + 1]);
        *(uint4*)&outh[(size_t)node * OUT_CH + l * 8] = *(uint4*)p;
    } else {
        float4 o0 = make_float4(acc[0], acc[1], acc[2], acc[3]);
        float4 o1 = make_float4(acc[4], acc[5], acc[6], acc[7]);
        *(float4*)&out_final[(size_t)node * OUT_CH + l * 8] = o0;
        *(float4*)&out_final[(size_t)node * OUT_CH + l * 8 + 4] = o1;
    }
}

// ---------------- launch: two concurrent chains inside the captured graph ----
extern "C" void kernel_launch(void* const* d_in, const int* in_sizes, int n_in,
                              void* d_out, int out_size) {
    const float* x  = (const float*)d_in[0];
    const void*  ei = d_in[1];
    const float* W1 = (const float*)d_in[2];
    const float* W2 = (const float*)d_in[3];
    const float* W3 = (const float*)d_in[4];
    float* out = (float*)d_out;

    const int ZB = (N_NODES + 1023) / 1024;          // 98
    const int GB = (N_NODES + GM - 1) / GM;          // 1563
    const int AB = (N_NODES * 8 + 255) / 256;        // 3125

    cudaStream_t s2;
    cudaStreamCreateWithFlags(&s2, cudaStreamNonBlocking);
    cudaEvent_t evF, evJ, evS1, evC;
    cudaEventCreateWithFlags(&evF,  cudaEventDisableTiming);
    cudaEventCreateWithFlags(&evJ,  cudaEventDisableTiming);
    cudaEventCreateWithFlags(&evS1, cudaEventDisableTiming);
    cudaEventCreateWithFlags(&evC,  cudaEventDisableTiming);

    // fork: s2 branches off the capture (default) stream at the start
    cudaEventRecord(evF, 0);
    cudaStreamWaitEvent(s2, evF, 0);

    // ---- chain B on s2: weight chain + GEMM (independent of edges) ----
    k_w23<<<IN_CH, OUT_CH, 0, s2>>>(W2, W3);
    k_wc<<<IN_CH, OUT_CH, 0, s2>>>(W1);
    k_gemm<<<GB, 256, 0, s2>>>(x);
    cudaEventRecord(evJ, s2);

    // ---- chain A on default stream: CSR build ----
    k_convert<<<2048, 256>>>(ei);       // dst-only read, hist + rank
    k_scan<<<SB, SCAN_T>>>();           // single-pass decoupled lookback
    cudaEventRecord(evS1, 0);           // last reader of g_cnt / g_state done
    k_fill<<<EB, 256>>>(ei);            // atomic-free scatter via ranks

    // clear g_cnt + g_state for the NEXT replay, on s2 (after gemm, after scan)
    cudaStreamWaitEvent(s2, evS1, 0);
    k_clear<<<ZB, 1024, 0, s2>>>();
    cudaEventRecord(evC, s2);           // s2 branch tail

    // join 1: agg needs g_t (chain B)
    cudaStreamWaitEvent(0, evJ, 0);

    k_agg<<<AB, 256>>>(0, out);
    k_agg<<<AB, 256>>>(1, out);
    k_agg<<<AB, 256>>>(2, out);

    // join 2: fold the s2 tail (k_clear) back into the origin stream so the
    // capture has no unjoined work; placed after agg so the clear overlaps them.
    cudaStreamWaitEvent(0, evC, 0);

    cudaEventDestroy(evF);
    cudaEventDestroy(evJ);
    cudaEventDestroy(evS1);
    cudaEventDestroy(evC);
    cudaStreamDestroy(s2);
}

// round 10
// speedup vs baseline: 1.5829x; 1.0134x over previous
#include <cuda_runtime.h>
#include <cuda_bf16.h>
#include <cuda_fp16.h>

#define N_NODES 100000
#define N_EDGES 1600000
#define IN_CH   128
#define OUT_CH  64
#define SCAN_T  512
#define SB ((N_NODES + SCAN_T - 1) / SCAN_T)   /* 196 */
#define EB ((N_EDGES + 255) / 256)             /* 6250 */

// ---------------- device scratch (static, allocation-free) ----------------
// g_cnt and g_state are ZERO at every kernel_launch entry: zero-init at module
// load (first call); k_fill re-zeroes them at the end of each call (it runs
// after k_scan, the last reader). Graph replays are sequential.
__device__ float              g_W23[IN_CH * OUT_CH];   // W2@W3   [128,64]
__device__ float              g_Wc[IN_CH * OUT_CH];    // W1@W23  [128,64]
__device__ int                g_rank[N_EDGES];         // edge rank within dst bucket
__device__ int                g_col[N_EDGES];          // src ids grouped by dst
__device__ int                g_off[N_NODES + 1];      // CSR row offsets
__device__ int                g_cnt[N_NODES];          // histogram (cleared by fill)
__device__ unsigned long long g_state[SB];             // lookback: (flag<<32)|value
__device__ __half             g_t[N_NODES * OUT_CH];   // ping (fp16 features)
__device__ __half             g_y[N_NODES * OUT_CH];   // pong (fp16 features)

// ---------------- convert: dst-half only -> histogram + rank ----------------
__global__ void k_convert(const void* ei) {
    // int64 => odd 32-bit words are high words == 0 (ids < 100000).
    // int32 => they are real src values (P(first 4 all zero) ~ 1e-20).
    const int* w = (const int*)ei;
    bool is64 = ((w[1] | w[3] | w[5] | w[7]) == 0);
    int tid = blockIdx.x * blockDim.x + threadIdx.x;
    int stride = gridDim.x * blockDim.x;
    for (int e = tid; e < N_EDGES; e += stride) {
        int d;
        if (is64) d = (int)((const long long*)ei)[(long long)N_EDGES + e];
        else      d = ((const int*)ei)[N_EDGES + e];
        g_rank[e] = atomicAdd(&g_cnt[d], 1);   // histogram + bucket rank in one
    }
}

// ---------------- single-pass scan: decoupled lookback ----------------
// grid = SB (196 blocks, all co-resident), block = 512.
__global__ void k_scan() {
    __shared__ int s[SCAN_T];
    __shared__ int sh_excl;
    int t = threadIdx.x, b = blockIdx.x;
    int idx = b * SCAN_T + t;
    int v = (idx < N_NODES) ? g_cnt[idx] : 0;
    s[t] = v;
    __syncthreads();
    for (int o = 1; o < SCAN_T; o <<= 1) {
        int a = (t >= o) ? s[t - o] : 0;
        __syncthreads();
        s[t] += a;
        __syncthreads();
    }
    int incl = s[t];
    int total = s[SCAN_T - 1];

    if (t == 0) {
        unsigned long long st = (b == 0)
            ? ((2ULL << 32) | (unsigned long long)(unsigned)total)
            : ((1ULL << 32) | (unsigned long long)(unsigned)total);
        atomicExch(&g_state[b], st);
    }

    if (b == 0) {
        if (t == 0) sh_excl = 0;
    } else if (t < 32) {
        int excl = 0;
        int p = b - 1;
        while (true) {
            int pi = p - t;
            unsigned long long stv;
            if (pi >= 0) {
                do { stv = atomicAdd(&g_state[pi], 0ULL); } while ((stv >> 32) == 0);
            } else {
                stv = (2ULL << 32);
            }
            unsigned flag = (unsigned)(stv >> 32);
            int val = (int)(unsigned)(stv & 0xffffffffULL);
            unsigned done_mask = __ballot_sync(0xffffffffu, flag == 2);
            int k = done_mask ? (__ffs(done_mask) - 1) : 31;
            int contrib = (t <= k) ? val : 0;
#pragma unroll
            for (int o = 16; o > 0; o >>= 1)
                contrib += __shfl_down_sync(0xffffffffu, contrib, o);
            if (t == 0) excl += contrib;
            if (done_mask) break;
            p -= 32;
        }
        if (t == 0) {
            atomicExch(&g_state[b],
                       (2ULL << 32) | (unsigned long long)(unsigned)(excl + total));
            sh_excl = excl;
        }
    }
    __syncthreads();
    int e0 = sh_excl;
    if (idx < N_NODES) g_off[idx] = e0 + incl - v;
    if (b == 0 && t == 0) g_off[N_NODES] = N_EDGES;
}

// ------- atomic-free CSR fill + clear of g_cnt/g_state for next replay -------
__global__ void k_fill(const void* ei) {
    const int* w = (const int*)ei;
    bool is64 = ((w[1] | w[3] | w[5] | w[7]) == 0);
    int e = blockIdx.x * blockDim.x + threadIdx.x;
    if (e < N_EDGES) {
        int s, d;
        if (is64) {
            const long long* p = (const long long*)ei;
            s = (int)p[e];
            d = (int)p[(long long)N_EDGES + e];
        } else {
            const int* p = (const int*)ei;
            s = p[e];
            d = p[N_EDGES + e];
        }
        g_col[g_off[d] + g_rank[e]] = s;
    }
    // clear for next graph replay (k_scan, the last reader, already ran)
    if (e < N_NODES) g_cnt[e] = 0;
    if (e < SB) g_state[e] = 0ULL;
}

// ---------------- weight chain: W23 = W2@W3 ; Wc = W1@W23 ----------------
__global__ void k_w23(const float* __restrict__ W2, const float* __restrict__ W3) {
    int k = blockIdx.x;      // 0..127
    int j = threadIdx.x;     // 0..63
    float s = 0.f;
#pragma unroll 8
    for (int m = 0; m < IN_CH; m++)
        s += W2[k * IN_CH + m] * W3[m * OUT_CH + j];
    g_W23[k * OUT_CH + j] = s;
}
__global__ void k_wc(const float* __restrict__ W1) {
    int k = blockIdx.x;      // 0..127
    int j = threadIdx.x;     // 0..63
    float s = 0.f;
#pragma unroll 8
    for (int m = 0; m < IN_CH; m++)
        s += W1[k * IN_CH + m] * g_W23[m * OUT_CH + j];
    g_Wc[k * OUT_CH + j] = s;
}

// ---------------- GEMM: t[100000,64] = x[100000,128] @ Wc[128,64] (fp16 out) --
#define GM 64
#define GK 64
__global__ __launch_bounds__(256) void k_gemm(const float* __restrict__ x) {
    __shared__ float XsT[GK][GM + 4];   // transposed: [k][row]
    __shared__ float Ws[GK][OUT_CH];    // [k][col]
    int row0 = blockIdx.x * GM;
    int tid = threadIdx.x;
    int ty = tid >> 4;        // 0..15 -> rows ty*4..+3
    int tx = tid & 15;        // 0..15 -> cols tx*4..+3
    float acc[4][4];
#pragma unroll
    for (int i = 0; i < 4; i++)
#pragma unroll
        for (int j = 0; j < 4; j++) acc[i][j] = 0.f;

    for (int kc = 0; kc < IN_CH; kc += GK) {
#pragma unroll
        for (int i = 0; i < 4; i++) {
            int slot = tid + i * 256;           // 0..1023 float4 slots
            int r = slot >> 4;                  // row 0..63
            int kq = slot & 15;                 // float4 idx within 64 k
            int grow = row0 + r;
            float4 v = make_float4(0.f, 0.f, 0.f, 0.f);
            if (grow < N_NODES)
                v = *(const float4*)&x[(long long)grow * IN_CH + kc + kq * 4];
            XsT[kq * 4 + 0][r] = v.x;
            XsT[kq * 4 + 1][r] = v.y;
            XsT[kq * 4 + 2][r] = v.z;
            XsT[kq * 4 + 3][r] = v.w;
        }
#pragma unroll
        for (int i = 0; i < 4; i++) {
            int slot = tid + i * 256;
            int k = slot >> 4;
            int nq = slot & 15;
            *(float4*)&Ws[k][nq * 4] =
                *(const float4*)&g_Wc[(kc + k) * OUT_CH + nq * 4];
        }
        __syncthreads();
#pragma unroll
        for (int k = 0; k < GK; k++) {
            float4 a = *(const float4*)&XsT[k][ty * 4];
            float4 b = *(const float4*)&Ws[k][tx * 4];
            float ar[4] = {a.x, a.y, a.z, a.w};
            float br[4] = {b.x, b.y, b.z, b.w};
#pragma unroll
            for (int i = 0; i < 4; i++)
#pragma unroll
                for (int j = 0; j < 4; j++) acc[i][j] += ar[i] * br[j];
        }
        __syncthreads();
    }
#pragma unroll
    for (int i = 0; i < 4; i++) {
        int grow = row0 + ty * 4 + i;
        if (grow < N_NODES) {
            __half2 p[2];
            p[0] = __floats2half2_rn(acc[i][0], acc[i][1]);
            p[1] = __floats2half2_rn(acc[i][2], acc[i][3]);
            *(uint2*)&g_t[(size_t)grow * OUT_CH + tx * 4] = *(uint2*)p;
        }
    }
}

// ------- CSR aggregation (fp16 gather, fp32 acc, 8-edge MLP) -------
__global__ __launch_bounds__(256) void k_agg(int phase, float* __restrict__ out_final) {
    const __half* __restrict__ in = (phase == 1) ? g_y : g_t;
    __half* __restrict__ outh = (phase == 0) ? g_y : g_t;

    int tid = blockIdx.x * blockDim.x + threadIdx.x;
    int node = tid >> 3;
    int l = tid & 7;
    if (node >= N_NODES) return;
    int s = g_off[node];
    int e = g_off[node + 1];
    float acc[8];
#pragma unroll
    for (int q = 0; q < 8; q++) acc[q] = 0.f;

    int i = s;
    // 8-edge unroll: 8 independent 16B gathers in flight per thread (MLP=8)
    for (; i + 8 <= e; i += 8) {
        int c[8];
#pragma unroll
        for (int u = 0; u < 8; u++) c[u] = __ldg(&g_col[i + u]);
        uint4 uu[8];
#pragma unroll
        for (int u = 0; u < 8; u++)
            uu[u] = *(const uint4*)&in[(size_t)c[u] * OUT_CH + l * 8];
#pragma unroll
        for (int u = 0; u < 8; u++) {
            const __half2* h = (const __half2*)&uu[u];
#pragma unroll
            for (int q = 0; q < 4; q++) {
                float2 f = __half22float2(h[q]);
                acc[2 * q + 0] += f.x;
                acc[2 * q + 1] += f.y;
            }
        }
    }
    for (; i + 4 <= e; i += 4) {
        int c[4];
#pragma unroll
        for (int u = 0; u < 4; u++) c[u] = __ldg(&g_col[i + u]);
        uint4 uu[4];
#pragma unroll
        for (int u = 0; u < 4; u++)
            uu[u] = *(const uint4*)&in[(size_t)c[u] * OUT_CH + l * 8];
#pragma unroll
        for (int u = 0; u < 4; u++) {
            const __half2* h = (const __half2*)&uu[u];
#pragma unroll
            for (int q = 0; q < 4; q++) {
                float2 f = __half22float2(h[q]);
                acc[2 * q + 0] += f.x;
                acc[2 * q + 1] += f.y;
            }
        }
    }
    for (; i < e; i++) {
        int c = __ldg(&g_col[i]);
        uint4 u = *(const uint4*)&in[(size_t)c * OUT_CH + l * 8];
        const __half2* h = (const __half2*)&u;
#pragma unroll
        for (int q = 0; q < 4; q++) {
            float2 f = __half22float2(h[q]);
            acc[2 * q + 0] += f.x;
            acc[2 * q + 1] += f.y;
        }
    }

    if (phase < 2) {
        __half2 p[4];
#pragma unroll
        for (int q = 0; q < 4; q++)
            p[q] = __floats2half2_rn(acc[2 * q], acc[2 * q + 1]);
        *(uint4*)&outh[(size_t)node * OUT_CH + l * 8] = *(uint4*)p;
    } else {
        float4 o0 = make_float4(acc[0], acc[1], acc[2], acc[3]);
        float4 o1 = make_float4(acc[4], acc[5], acc[6], acc[7]);
        *(float4*)&out_final[(size_t)node * OUT_CH + l * 8] = o0;
        *(float4*)&out_final[(size_t)node * OUT_CH + l * 8 + 4] = o1;
    }
}

// ---------------- launch: two concurrent chains inside the captured graph ----
extern "C" void kernel_launch(void* const* d_in, const int* in_sizes, int n_in,
                              void* d_out, int out_size) {
    const float* x  = (const float*)d_in[0];
    const void*  ei = d_in[1];
    const float* W1 = (const float*)d_in[2];
    const float* W2 = (const float*)d_in[3];
    const float* W3 = (const float*)d_in[4];
    float* out = (float*)d_out;

    const int GB = (N_NODES + GM - 1) / GM;          // 1563
    const int AB = (N_NODES * 8 + 255) / 256;        // 3125

    cudaStream_t s2;
    cudaStreamCreateWithFlags(&s2, cudaStreamNonBlocking);
    cudaEvent_t evF, evJ;
    cudaEventCreateWithFlags(&evF, cudaEventDisableTiming);
    cudaEventCreateWithFlags(&evJ, cudaEventDisableTiming);

    // fork: s2 branches off the capture (default) stream at the start
    cudaEventRecord(evF, 0);
    cudaStreamWaitEvent(s2, evF, 0);

    // ---- chain B on s2: weight chain + GEMM (independent of edges) ----
    k_w23<<<IN_CH, OUT_CH, 0, s2>>>(W2, W3);
    k_wc<<<IN_CH, OUT_CH, 0, s2>>>(W1);
    k_gemm<<<GB, 256, 0, s2>>>(x);
    cudaEventRecord(evJ, s2);

    // ---- chain A on default stream: CSR build ----
    k_convert<<<2048, 256>>>(ei);       // dst-only read, hist + rank
    k_scan<<<SB, SCAN_T>>>();           // single-pass decoupled lookback
    k_fill<<<EB, 256>>>(ei);            // atomic-free scatter + state clear

    // join: agg needs g_t (chain B) and CSR (chain A)
    cudaStreamWaitEvent(0, evJ, 0);

    k_agg<<<AB, 256>>>(0, out);
    k_agg<<<AB, 256>>>(1, out);
    k_agg<<<AB, 256>>>(2, out);

    cudaEventDestroy(evF);
    cudaEventDestroy(evJ);
    cudaStreamDestroy(s2);
}

// round 11
// speedup vs baseline: 1.6472x; 1.0406x over previous
#include <cuda_runtime.h>
#include <cuda_bf16.h>
#include <cuda_fp16.h>

#define N_NODES 100000
#define N_EDGES 1600000
#define IN_CH   128
#define OUT_CH  64
#define SCAN_T  512
#define SB ((N_NODES + SCAN_T - 1) / SCAN_T)   /* 196 */
#define EB ((N_EDGES + 255) / 256)             /* 6250 */
#define DB 64                                  /* degree bins */
#define NB ((N_NODES + 1023) / 1024)           /* 98 node blocks */

// ---------------- device scratch (static, allocation-free) ----------------
// g_cnt and g_state are ZERO at every kernel_launch entry: zero-init at module
// load (first call); k_fill re-zeroes them each call. All degree-perm arrays
// are fully overwritten each call (no persistence).
__device__ float              g_W23[IN_CH * OUT_CH];   // W2@W3   [128,64]
__device__ float              g_Wc[IN_CH * OUT_CH];    // W1@W23  [128,64]
__device__ int                g_rank[N_EDGES];         // edge rank within dst bucket
__device__ int                g_col[N_EDGES];          // src ids grouped by dst
__device__ int                g_off[N_NODES + 1];      // CSR row offsets
__device__ int                g_cnt[N_NODES];          // histogram (cleared by fill)
__device__ unsigned long long g_state[SB];             // lookback: (flag<<32)|value
__device__ int                g_drank[N_NODES];        // node rank within (bin,block)
__device__ int                g_bcnt[DB * NB];         // per-(bin,block) counts
__device__ int                g_bbase[DB * NB];        // scanned bases
__device__ int                g_perm[N_NODES];         // degree-sorted node order
__device__ __half             g_t[N_NODES * OUT_CH];   // ping (fp16 features)
__device__ __half             g_y[N_NODES * OUT_CH];   // pong (fp16 features)

// ---------------- convert: dst-half only -> histogram + rank ----------------
__global__ void k_convert(const void* ei) {
    const int* w = (const int*)ei;
    bool is64 = ((w[1] | w[3] | w[5] | w[7]) == 0);
    int tid = blockIdx.x * blockDim.x + threadIdx.x;
    int stride = gridDim.x * blockDim.x;
    for (int e = tid; e < N_EDGES; e += stride) {
        int d;
        if (is64) d = (int)((const long long*)ei)[(long long)N_EDGES + e];
        else      d = ((const int*)ei)[N_EDGES + e];
        g_rank[e] = atomicAdd(&g_cnt[d], 1);
    }
}

// ---------------- single-pass scan: decoupled lookback ----------------
__global__ void k_scan() {
    __shared__ int s[SCAN_T];
    __shared__ int sh_excl;
    int t = threadIdx.x, b = blockIdx.x;
    int idx = b * SCAN_T + t;
    int v = (idx < N_NODES) ? g_cnt[idx] : 0;
    s[t] = v;
    __syncthreads();
    for (int o = 1; o < SCAN_T; o <<= 1) {
        int a = (t >= o) ? s[t - o] : 0;
        __syncthreads();
        s[t] += a;
        __syncthreads();
    }
    int incl = s[t];
    int total = s[SCAN_T - 1];

    if (t == 0) {
        unsigned long long st = (b == 0)
            ? ((2ULL << 32) | (unsigned long long)(unsigned)total)
            : ((1ULL << 32) | (unsigned long long)(unsigned)total);
        atomicExch(&g_state[b], st);
    }

    if (b == 0) {
        if (t == 0) sh_excl = 0;
    } else if (t < 32) {
        int excl = 0;
        int p = b - 1;
        while (true) {
            int pi = p - t;
            unsigned long long stv;
            if (pi >= 0) {
                do { stv = atomicAdd(&g_state[pi], 0ULL); } while ((stv >> 32) == 0);
            } else {
                stv = (2ULL << 32);
            }
            unsigned flag = (unsigned)(stv >> 32);
            int val = (int)(unsigned)(stv & 0xffffffffULL);
            unsigned done_mask = __ballot_sync(0xffffffffu, flag == 2);
            int k = done_mask ? (__ffs(done_mask) - 1) : 31;
            int contrib = (t <= k) ? val : 0;
#pragma unroll
            for (int o = 16; o > 0; o >>= 1)
                contrib += __shfl_down_sync(0xffffffffu, contrib, o);
            if (t == 0) excl += contrib;
            if (done_mask) break;
            p -= 32;
        }
        if (t == 0) {
            atomicExch(&g_state[b],
                       (2ULL << 32) | (unsigned long long)(unsigned)(excl + total));
            sh_excl = excl;
        }
    }
    __syncthreads();
    int e0 = sh_excl;
    if (idx < N_NODES) g_off[idx] = e0 + incl - v;
    if (b == 0 && t == 0) g_off[N_NODES] = N_EDGES;
}

// ------- atomic-free CSR fill + clear of g_cnt/g_state for next replay -------
__global__ void k_fill(const void* ei) {
    const int* w = (const int*)ei;
    bool is64 = ((w[1] | w[3] | w[5] | w[7]) == 0);
    int e = blockIdx.x * blockDim.x + threadIdx.x;
    if (e < N_EDGES) {
        int s, d;
        if (is64) {
            const long long* p = (const long long*)ei;
            s = (int)p[e];
            d = (int)p[(long long)N_EDGES + e];
        } else {
            const int* p = (const int*)ei;
            s = p[e];
            d = p[N_EDGES + e];
        }
        g_col[g_off[d] + g_rank[e]] = s;
    }
    if (e < N_NODES) g_cnt[e] = 0;
    if (e < SB) g_state[e] = 0ULL;
}

// ---------------- degree binning: smem hist + local rank ----------------
__global__ __launch_bounds__(1024) void k_dcount() {
    __shared__ int h[DB];
    int t = threadIdx.x, b = blockIdx.x;
    if (t < DB) h[t] = 0;
    __syncthreads();
    int n = b * 1024 + t;
    if (n < N_NODES) {
        int d = min(g_off[n + 1] - g_off[n], DB - 1);
        g_drank[n] = atomicAdd(&h[d], 1);
    }
    __syncthreads();
    if (t < DB) g_bcnt[t * NB + b] = h[t];
}

// scan the DB x NB count matrix (bin-major): one block of 1024 (32 warps)
__global__ __launch_bounds__(1024) void k_dscan2() {
    __shared__ int btot[DB];
    __shared__ int bbase[DB];
    int t = threadIdx.x, lane = t & 31, w = t >> 5;   // w: 0..31, 2 bins each
#pragma unroll
    for (int q = 0; q < 2; q++) {
        int d = 2 * w + q;
        int carry = 0;
        for (int c = 0; c < (NB + 31) / 32; c++) {
            int i = c * 32 + lane;
            int v = (i < NB) ? g_bcnt[d * NB + i] : 0;
            int x = v;
#pragma unroll
            for (int o = 1; o < 32; o <<= 1) {
                int nn = __shfl_up_sync(0xffffffffu, x, o);
                if (lane >= o) x += nn;
            }
            if (i < NB) g_bbase[d * NB + i] = carry + x - v;
            carry += __shfl_sync(0xffffffffu, x, 31);
        }
        if (lane == 0) btot[d] = carry;
    }
    __syncthreads();
    if (w == 0) {
        int carry = 0;
#pragma unroll
        for (int c = 0; c < 2; c++) {
            int i = c * 32 + lane;
            int v = btot[i];
            int x = v;
#pragma unroll
            for (int o = 1; o < 32; o <<= 1) {
                int nn = __shfl_up_sync(0xffffffffu, x, o);
                if (lane >= o) x += nn;
            }
            bbase[i] = carry + x - v;
            carry += __shfl_sync(0xffffffffu, x, 31);
        }
    }
    __syncthreads();
#pragma unroll
    for (int q = 0; q < 2; q++) {
        int d = 2 * w + q;
        int base = bbase[d];
        for (int c = 0; c < (NB + 31) / 32; c++) {
            int i = c * 32 + lane;
            if (i < NB) g_bbase[d * NB + i] += base;
        }
    }
}

__global__ __launch_bounds__(1024) void k_dperm() {
    int t = threadIdx.x, b = blockIdx.x;
    int n = b * 1024 + t;
    if (n < N_NODES) {
        int d = min(g_off[n + 1] - g_off[n], DB - 1);
        g_perm[g_bbase[d * NB + b] + g_drank[n]] = n;
    }
}

// ---------------- weight chain: W23 = W2@W3 ; Wc = W1@W23 ----------------
__global__ void k_w23(const float* __restrict__ W2, const float* __restrict__ W3) {
    int k = blockIdx.x;
    int j = threadIdx.x;
    float s = 0.f;
#pragma unroll 8
    for (int m = 0; m < IN_CH; m++)
        s += W2[k * IN_CH + m] * W3[m * OUT_CH + j];
    g_W23[k * OUT_CH + j] = s;
}
__global__ void k_wc(const float* __restrict__ W1) {
    int k = blockIdx.x;
    int j = threadIdx.x;
    float s = 0.f;
#pragma unroll 8
    for (int m = 0; m < IN_CH; m++)
        s += W1[k * IN_CH + m] * g_W23[m * OUT_CH + j];
    g_Wc[k * OUT_CH + j] = s;
}

// ---------------- GEMM: t[100000,64] = x[100000,128] @ Wc[128,64] (fp16 out) --
#define GM 64
#define GK 64
__global__ __launch_bounds__(256) void k_gemm(const float* __restrict__ x) {
    __shared__ float XsT[GK][GM + 4];
    __shared__ float Ws[GK][OUT_CH];
    int row0 = blockIdx.x * GM;
    int tid = threadIdx.x;
    int ty = tid >> 4;
    int tx = tid & 15;
    float acc[4][4];
#pragma unroll
    for (int i = 0; i < 4; i++)
#pragma unroll
        for (int j = 0; j < 4; j++) acc[i][j] = 0.f;

    for (int kc = 0; kc < IN_CH; kc += GK) {
#pragma unroll
        for (int i = 0; i < 4; i++) {
            int slot = tid + i * 256;
            int r = slot >> 4;
            int kq = slot & 15;
            int grow = row0 + r;
            float4 v = make_float4(0.f, 0.f, 0.f, 0.f);
            if (grow < N_NODES)
                v = *(const float4*)&x[(long long)grow * IN_CH + kc + kq * 4];
            XsT[kq * 4 + 0][r] = v.x;
            XsT[kq * 4 + 1][r] = v.y;
            XsT[kq * 4 + 2][r] = v.z;
            XsT[kq * 4 + 3][r] = v.w;
        }
#pragma unroll
        for (int i = 0; i < 4; i++) {
            int slot = tid + i * 256;
            int k = slot >> 4;
            int nq = slot & 15;
            *(float4*)&Ws[k][nq * 4] =
                *(const float4*)&g_Wc[(kc + k) * OUT_CH + nq * 4];
        }
        __syncthreads();
#pragma unroll
        for (int k = 0; k < GK; k++) {
            float4 a = *(const float4*)&XsT[k][ty * 4];
            float4 b = *(const float4*)&Ws[k][tx * 4];
            float ar[4] = {a.x, a.y, a.z, a.w};
            float br[4] = {b.x, b.y, b.z, b.w};
#pragma unroll
            for (int i = 0; i < 4; i++)
#pragma unroll
                for (int j = 0; j < 4; j++) acc[i][j] += ar[i] * br[j];
        }
        __syncthreads();
    }
#pragma unroll
    for (int i = 0; i < 4; i++) {
        int grow = row0 + ty * 4 + i;
        if (grow < N_NODES) {
            __half2 p[2];
            p[0] = __floats2half2_rn(acc[i][0], acc[i][1]);
            p[1] = __floats2half2_rn(acc[i][2], acc[i][3]);
            *(uint2*)&g_t[(size_t)grow * OUT_CH + tx * 4] = *(uint2*)p;
        }
    }
}

// ------- CSR aggregation (fp16 gather, fp32 acc, degree-binned order) -------
__global__ __launch_bounds__(256) void k_agg(int phase, float* __restrict__ out_final) {
    const __half* __restrict__ in = (phase == 1) ? g_y : g_t;
    __half* __restrict__ outh = (phase == 0) ? g_y : g_t;

    int tid = blockIdx.x * blockDim.x + threadIdx.x;
    int p = tid >> 3;
    int l = tid & 7;
    if (p >= N_NODES) return;
    int node = __ldg(&g_perm[p]);      // degree-binned order: uniform warps
    int s = g_off[node];
    int e = g_off[node + 1];
    float acc[8];
#pragma unroll
    for (int q = 0; q < 8; q++) acc[q] = 0.f;

    int i = s;
    for (; i + 8 <= e; i += 8) {
        int c[8];
#pragma unroll
        for (int u = 0; u < 8; u++) c[u] = __ldg(&g_col[i + u]);
        uint4 uu[8];
#pragma unroll
        for (int u = 0; u < 8; u++)
            uu[u] = *(const uint4*)&in[(size_t)c[u] * OUT_CH + l * 8];
#pragma unroll
        for (int u = 0; u < 8; u++) {
            const __half2* h = (const __half2*)&uu[u];
#pragma unroll
            for (int q = 0; q < 4; q++) {
                float2 f = __half22float2(h[q]);
                acc[2 * q + 0] += f.x;
                acc[2 * q + 1] += f.y;
            }
        }
    }
    for (; i + 4 <= e; i += 4) {
        int c[4];
#pragma unroll
        for (int u = 0; u < 4; u++) c[u] = __ldg(&g_col[i + u]);
        uint4 uu[4];
#pragma unroll
        for (int u = 0; u < 4; u++)
            uu[u] = *(const uint4*)&in[(size_t)c[u] * OUT_CH + l * 8];
#pragma unroll
        for (int u = 0; u < 4; u++) {
            const __half2* h = (const __half2*)&uu[u];
#pragma unroll
            for (int q = 0; q < 4; q++) {
                float2 f = __half22float2(h[q]);
                acc[2 * q + 0] += f.x;
                acc[2 * q + 1] += f.y;
            }
        }
    }
    for (; i < e; i++) {
        int c = __ldg(&g_col[i]);
        uint4 u = *(const uint4*)&in[(size_t)c * OUT_CH + l * 8];
        const __half2* h = (const __half2*)&u;
#pragma unroll
        for (int q = 0; q < 4; q++) {
            float2 f = __half22float2(h[q]);
            acc[2 * q + 0] += f.x;
            acc[2 * q + 1] += f.y;
        }
    }

    if (phase < 2) {
        __half2 pk[4];
#pragma unroll
        for (int q = 0; q < 4; q++)
            pk[q] = __floats2half2_rn(acc[2 * q], acc[2 * q + 1]);
        *(uint4*)&outh[(size_t)node * OUT_CH + l * 8] = *(uint4*)pk;
    } else {
        float4 o0 = make_float4(acc[0], acc[1], acc[2], acc[3]);
        float4 o1 = make_float4(acc[4], acc[5], acc[6], acc[7]);
        *(float4*)&out_final[(size_t)node * OUT_CH + l * 8] = o0;
        *(float4*)&out_final[(size_t)node * OUT_CH + l * 8 + 4] = o1;
    }
}

// ---------------- launch: three forked chains inside the captured graph ----
extern "C" void kernel_launch(void* const* d_in, const int* in_sizes, int n_in,
                              void* d_out, int out_size) {
    const float* x  = (const float*)d_in[0];
    const void*  ei = d_in[1];
    const float* W1 = (const float*)d_in[2];
    const float* W2 = (const float*)d_in[3];
    const float* W3 = (const float*)d_in[4];
    float* out = (float*)d_out;

    const int GB = (N_NODES + GM - 1) / GM;          // 1563
    const int AB = (N_NODES * 8 + 255) / 256;        // 3125

    cudaStream_t s2, s3;
    cudaStreamCreateWithFlags(&s2, cudaStreamNonBlocking);
    cudaStreamCreateWithFlags(&s3, cudaStreamNonBlocking);
    cudaEvent_t evF, evJ, evScan, evD;
    cudaEventCreateWithFlags(&evF,    cudaEventDisableTiming);
    cudaEventCreateWithFlags(&evJ,    cudaEventDisableTiming);
    cudaEventCreateWithFlags(&evScan, cudaEventDisableTiming);
    cudaEventCreateWithFlags(&evD,    cudaEventDisableTiming);

    // fork s2 at entry
    cudaEventRecord(evF, 0);
    cudaStreamWaitEvent(s2, evF, 0);

    // ---- chain B on s2: weight chain + GEMM ----
    k_w23<<<IN_CH, OUT_CH, 0, s2>>>(W2, W3);
    k_wc<<<IN_CH, OUT_CH, 0, s2>>>(W1);
    k_gemm<<<GB, 256, 0, s2>>>(x);
    cudaEventRecord(evJ, s2);

    // ---- chain A on default stream: CSR build ----
    k_convert<<<2048, 256>>>(ei);
    k_scan<<<SB, SCAN_T>>>();
    cudaEventRecord(evScan, 0);         // g_off ready -> fork degree chain
    k_fill<<<EB, 256>>>(ei);

    // ---- chain C on s3: degree-binned permutation (needs only g_off) ----
    cudaStreamWaitEvent(s3, evScan, 0);
    k_dcount<<<NB, 1024, 0, s3>>>();
    k_dscan2<<<1, 1024, 0, s3>>>();
    k_dperm<<<NB, 1024, 0, s3>>>();
    cudaEventRecord(evD, s3);

    // join: agg needs g_t (B), CSR (A), perm (C)
    cudaStreamWaitEvent(0, evJ, 0);
    cudaStreamWaitEvent(0, evD, 0);

    k_agg<<<AB, 256>>>(0, out);
    k_agg<<<AB, 256>>>(1, out);
    k_agg<<<AB, 256>>>(2, out);

    cudaEventDestroy(evF);
    cudaEventDestroy(evJ);
    cudaEventDestroy(evScan);
    cudaEventDestroy(evD);
    cudaStreamDestroy(s2);
    cudaStreamDestroy(s3);
}